// round 5
// baseline (speedup 1.0000x reference)
#include <cuda_runtime.h>
#include <cstdint>
#include <cstddef>

#define SEQ   128
#define BATCH 256
#define OBS   64
#define HID   1024
#define GATES 4096
#define NBLK 128
#define NTHR 256
#define BM 64
#define BN 128
#define BK 16

// Device scratch (allocations forbidden; __device__ globals are the workaround)
__device__ float g_h[2 * BATCH * HID];
__device__ float g_c[2 * BATCH * HID];
__device__ float g_gates[BATCH * GATES];
__device__ float g_hs[(size_t)SEQ * BATCH * HID];
__device__ float g_a1[(size_t)SEQ * BATCH * 512];
__device__ float g_a2[(size_t)SEQ * BATCH * 128];
__device__ float g_a3[(size_t)SEQ * BATCH * 64];

// Grid barrier: monotonic counters -> safe across graph replays. All 128
// blocks are co-resident (1 small block per SM, 148+ SMs), so spinning is safe.
__device__ unsigned g_arr = 0;
__device__ volatile unsigned g_rel = 0;

__device__ __forceinline__ void grid_sync() {
    __syncthreads();
    if (threadIdx.x == 0) {
        __threadfence();
        unsigned v = atomicAdd(&g_arr, 1u);
        unsigned target = v / NBLK + 1u;
        if ((v % NBLK) == NBLK - 1u) g_rel = target;
        else while (g_rel < target) { }
        __threadfence();
    }
    __syncthreads();
}

union F2 { unsigned long long u; float2 f; };
__device__ __forceinline__ float sigm(float x) { return 1.0f / (1.0f + expf(-x)); }

// Blackwell packed dual-FMA: d(2xf32) += a*b
#define FMA2(d, a, b) asm("fma.rn.f32x2 %0, %1, %2, %0;" : "+l"(d) : "l"(a), "l"(b))
#define DUP2(d, s)    asm("mov.b64 %0, {%1, %1};" : "=l"(d) : "r"(s))

// C[M,N] = [A0 | A1*mask] @ [B0 | B1]^T + bias0 + bias1, optional ELU.
// Tile 64x128, BK=16, 256 threads, 4x8 per-thread accumulator as f32x2 pairs.
__device__ void gemm(int M, int N,
                     const float* A0, int lda0, int K0,
                     const float* A1, int lda1, int K1,
                     const float* B0, int ldb0,
                     const float* B1, int ldb1,
                     const float* bias0, const float* bias1,
                     const int* done_t,
                     float* C, int ldc, int act)
{
    __shared__ __align__(16) float As[BK][BM];
    __shared__ __align__(16) float Bs[BK][BN];
    __shared__ float Ms[BM];

    const int tid  = threadIdx.x;
    const int tm4  = (tid >> 4) << 2;
    const int tn4  = (tid & 15) << 2;
    const int arow = tid >> 2;
    const int ak   = (tid & 3) << 2;
    const int bnr  = tid >> 1;
    const int bk8  = (tid & 1) << 3;

    const int ntm  = M / BM;
    const int ntn  = (N + BN - 1) / BN;
    const int kt0  = K0 / BK;
    const int ktot = kt0 + K1 / BK;
    const bool hasmask = (done_t != nullptr);

    for (int tt = blockIdx.x; tt < ntm * ntn; tt += NBLK) {
        const int m0 = (tt % ntm) * BM;
        const int n0 = (tt / ntm) * BN;

        if (hasmask && tid < BM) Ms[tid] = 1.0f - (float)done_t[m0 + tid];

        F2 acc[4][4];
        #pragma unroll
        for (int i = 0; i < 4; i++)
            #pragma unroll
            for (int j = 0; j < 4; j++) acc[i][j].u = 0ull;

        float4 pa, pb0, pb1;
        bool pmask = false;
        pa = *(const float4*)(A0 + (size_t)(m0 + arow) * lda0 + ak);
        {
            int gn = n0 + bnr;
            if (gn < N) {
                const float* bp = B0 + (size_t)gn * ldb0 + bk8;
                pb0 = *(const float4*)bp;
                pb1 = *(const float4*)(bp + 4);
            } else { pb0 = make_float4(0.f,0.f,0.f,0.f); pb1 = pb0; }
        }

        for (int kt = 0; kt < ktot; ++kt) {
            __syncthreads();
            {
                float msc = pmask ? Ms[arow] : 1.0f;
                As[ak+0][arow] = pa.x * msc; As[ak+1][arow] = pa.y * msc;
                As[ak+2][arow] = pa.z * msc; As[ak+3][arow] = pa.w * msc;
                Bs[bk8+0][bnr] = pb0.x; Bs[bk8+1][bnr] = pb0.y;
                Bs[bk8+2][bnr] = pb0.z; Bs[bk8+3][bnr] = pb0.w;
                Bs[bk8+4][bnr] = pb1.x; Bs[bk8+5][bnr] = pb1.y;
                Bs[bk8+6][bnr] = pb1.z; Bs[bk8+7][bnr] = pb1.w;
            }
            __syncthreads();

            if (kt + 1 < ktot) {
                const int k2 = kt + 1;
                const float* A; int lda; const float* Bp; int ldb; int kl;
                if (k2 < kt0) { A = A0; lda = lda0; Bp = B0; ldb = ldb0; kl = k2 * BK;          pmask = false;   }
                else          { A = A1; lda = lda1; Bp = B1; ldb = ldb1; kl = (k2 - kt0) * BK; pmask = hasmask; }
                pa = *(const float4*)(A + (size_t)(m0 + arow) * lda + kl + ak);
                int gn = n0 + bnr;
                if (gn < N) {
                    const float* bp = Bp + (size_t)gn * ldb + kl + bk8;
                    pb0 = *(const float4*)bp;
                    pb1 = *(const float4*)(bp + 4);
                } else { pb0 = make_float4(0.f,0.f,0.f,0.f); pb1 = pb0; }
            }

            #pragma unroll
            for (int kk = 0; kk < BK; kk++) {
                float4 av      = *(const float4*)&As[kk][tm4];
                ulonglong2 bv0 = *(const ulonglong2*)&Bs[kk][tn4];
                ulonglong2 bv1 = *(const ulonglong2*)&Bs[kk][64 + tn4];
                unsigned long long aa;
                DUP2(aa, __float_as_uint(av.x));
                FMA2(acc[0][0].u, aa, bv0.x); FMA2(acc[0][1].u, aa, bv0.y);
                FMA2(acc[0][2].u, aa, bv1.x); FMA2(acc[0][3].u, aa, bv1.y);
                DUP2(aa, __float_as_uint(av.y));
                FMA2(acc[1][0].u, aa, bv0.x); FMA2(acc[1][1].u, aa, bv0.y);
                FMA2(acc[1][2].u, aa, bv1.x); FMA2(acc[1][3].u, aa, bv1.y);
                DUP2(aa, __float_as_uint(av.z));
                FMA2(acc[2][0].u, aa, bv0.x); FMA2(acc[2][1].u, aa, bv0.y);
                FMA2(acc[2][2].u, aa, bv1.x); FMA2(acc[2][3].u, aa, bv1.y);
                DUP2(aa, __float_as_uint(av.w));
                FMA2(acc[3][0].u, aa, bv0.x); FMA2(acc[3][1].u, aa, bv0.y);
                FMA2(acc[3][2].u, aa, bv1.x); FMA2(acc[3][3].u, aa, bv1.y);
            }
        }

        #pragma unroll
        for (int i = 0; i < 4; i++) {
            const int r = m0 + tm4 + i;
            #pragma unroll
            for (int hh = 0; hh < 2; hh++) {
                #pragma unroll
                for (int p = 0; p < 2; p++) {
                    float2 v = acc[i][hh * 2 + p].f;
                    const int c = n0 + hh * 64 + tn4 + p * 2;
                    #pragma unroll
                    for (int q = 0; q < 2; q++) {
                        float vv = q ? v.y : v.x;
                        if (c + q < N) {
                            float b = bias0 ? bias0[c + q] : 0.0f;
                            if (bias1) b += bias1[c + q];
                            float o = vv + b;
                            if (act) o = o > 0.0f ? o : expm1f(o);
                            C[(size_t)r * ldc + c + q] = o;
                        }
                    }
                }
            }
        }
    }
}

// Pointwise LSTM cell from g_gates. PyTorch gate order i,f,g,o.
__device__ void cell_phase(float* h_state, float* c_state,
                           const int* done_t, float* hs_out)
{
    const int stride = NBLK * NTHR;
    for (int idx = blockIdx.x * NTHR + threadIdx.x; idx < BATCH * HID; idx += stride) {
        const int b = idx >> 10;
        const int j = idx & (HID - 1);
        const float m = 1.0f - (float)done_t[b];
        const float* g = g_gates + (size_t)b * GATES;
        const float ig = sigm(g[j]);
        const float fg = sigm(g[HID + j]);
        const float gg = tanhf(g[2 * HID + j]);
        const float og = sigm(g[3 * HID + j]);
        const float c = fg * (c_state[idx] * m) + ig * gg;
        const float h = og * tanhf(c);
        c_state[idx] = c;
        h_state[idx] = h;
        if (hs_out) hs_out[idx] = h;
    }
}

__device__ void layernorm_phase(const float* __restrict__ gamma,
                                const float* __restrict__ beta)
{
    const int gwid = (blockIdx.x * NTHR + threadIdx.x) >> 5;
    const int lane = threadIdx.x & 31;
    const int nwarps = NBLK * NTHR / 32;
    for (int r = gwid; r < SEQ * BATCH; r += nwarps) {
        float* row = g_hs + (size_t)r * HID;
        float s = 0.f, ss = 0.f;
        for (int j = lane; j < HID; j += 32) { float v = row[j]; s += v; ss += v * v; }
        #pragma unroll
        for (int o = 16; o; o >>= 1) {
            s  += __shfl_xor_sync(0xffffffffu, s, o);
            ss += __shfl_xor_sync(0xffffffffu, ss, o);
        }
        const float mu   = s * (1.0f / HID);
        const float var  = ss * (1.0f / HID) - mu * mu;
        const float rstd = rsqrtf(var + 1e-5f);
        for (int j = lane; j < HID; j += 32)
            row[j] = (row[j] - mu) * rstd * gamma[j] + beta[j];
    }
}

__global__ __launch_bounds__(NTHR)
void critic_kernel(
    const float* __restrict__ x, const int* __restrict__ done,
    const float* __restrict__ h0, const float* __restrict__ c0,
    const float* __restrict__ Wih0, const float* __restrict__ Whh0,
    const float* __restrict__ bih0, const float* __restrict__ bhh0,
    const float* __restrict__ Wih1, const float* __restrict__ Whh1,
    const float* __restrict__ bih1, const float* __restrict__ bhh1,
    const float* __restrict__ lng,  const float* __restrict__ lnb,
    const float* __restrict__ W1,   const float* __restrict__ b1,
    const float* __restrict__ W2,   const float* __restrict__ b2,
    const float* __restrict__ W3,   const float* __restrict__ b3,
    const float* __restrict__ Wv,   const float* __restrict__ bv,
    float* __restrict__ out, int out_size)
{
    const int stride = NBLK * NTHR;
    const int gtid = blockIdx.x * NTHR + threadIdx.x;

    for (int i = gtid; i < 2 * BATCH * HID; i += stride) { g_h[i] = h0[i]; g_c[i] = c0[i]; }
    grid_sync();

    for (int t = 0; t < SEQ; ++t) {
        const int* dt = done + t * BATCH;

        gemm(BATCH, GATES, x + (size_t)t * BATCH * OBS, OBS, OBS,
             g_h, HID, HID, Wih0, OBS, Whh0, HID,
             bih0, bhh0, dt, g_gates, GATES, 0);
        grid_sync();
        cell_phase(g_h, g_c, dt, nullptr);
        grid_sync();

        gemm(BATCH, GATES, g_h, HID, HID,
             g_h + BATCH * HID, HID, HID, Wih1, HID, Whh1, HID,
             bih1, bhh1, dt, g_gates, GATES, 0);
        grid_sync();
        cell_phase(g_h + BATCH * HID, g_c + BATCH * HID, dt,
                   g_hs + (size_t)t * BATCH * HID);
        grid_sync();
    }

    layernorm_phase(lng, lnb);
    grid_sync();

    gemm(SEQ * BATCH, 512, g_hs, HID, HID, nullptr, 0, 0,
         W1, HID, nullptr, 0, b1, nullptr, nullptr, g_a1, 512, 1);
    grid_sync();
    gemm(SEQ * BATCH, 128, g_a1, 512, 512, nullptr, 0, 0,
         W2, 512, nullptr, 0, b2, nullptr, nullptr, g_a2, 128, 1);
    grid_sync();
    gemm(SEQ * BATCH, 64, g_a2, 128, 128, nullptr, 0, 0,
         W3, 128, nullptr, 0, b3, nullptr, nullptr, g_a3, 64, 1);
    grid_sync();

    for (int r = gtid; r < SEQ * BATCH; r += stride) {
        const float* a = g_a3 + (size_t)r * 64;
        float s = bv[0];
        #pragma unroll
        for (int k = 0; k < 64; k++) s += a[k] * Wv[k];
        out[r] = s;
    }
    if (out_size >= SEQ * BATCH + 4 * BATCH * HID) {
        float* oh = out + SEQ * BATCH;
        float* oc = oh + 2 * BATCH * HID;
        for (int i = gtid; i < 2 * BATCH * HID; i += stride) {
            oh[i] = g_h[i];
            oc[i] = g_c[i];
        }
    }
}

extern "C" void kernel_launch(void* const* d_in, const int* in_sizes, int n_in,
                              void* d_out, int out_size)
{
    critic_kernel<<<NBLK, NTHR>>>(
        (const float*)d_in[0],  (const int*)d_in[1],
        (const float*)d_in[2],  (const float*)d_in[3],
        (const float*)d_in[4],  (const float*)d_in[5],
        (const float*)d_in[6],  (const float*)d_in[7],
        (const float*)d_in[8],  (const float*)d_in[9],
        (const float*)d_in[10], (const float*)d_in[11],
        (const float*)d_in[12], (const float*)d_in[13],
        (const float*)d_in[14], (const float*)d_in[15],
        (const float*)d_in[16], (const float*)d_in[17],
        (const float*)d_in[18], (const float*)d_in[19],
        (const float*)d_in[20], (const float*)d_in[21],
        (float*)d_out, out_size);
}

// round 10
// speedup vs baseline: 1.0684x; 1.0684x over previous
#include <cuda_runtime.h>
#include <cstdint>
#include <cstddef>

#define SEQ   128
#define BATCH 256
#define OBS   64
#define HID   1024
#define GATES 4096
#define NBLK  128
#define NTHR  256
#define BM    64
#define BN    128
#define BK    16

// ---- device scratch ----
__device__ float g_h[2 * BATCH * HID];
__device__ float g_c[2 * BATCH * HID];
__device__ float g_gates[BATCH * GATES];
__device__ float g_hs[(size_t)SEQ * BATCH * HID];
__device__ float g_a1[(size_t)SEQ * BATCH * 512];
__device__ float g_a2[(size_t)SEQ * BATCH * 128];
__device__ float g_a3[(size_t)SEQ * BATCH * 64];

// ---- grid barrier: monotonic, graph-replay-safe ----
__device__ unsigned g_arr = 0;
__device__ volatile unsigned g_rel = 0;

__device__ __forceinline__ void grid_sync() {
    __syncthreads();
    if (threadIdx.x == 0) {
        __threadfence();
        unsigned v = atomicAdd(&g_arr, 1u);
        unsigned target = v / NBLK + 1u;
        if ((v % NBLK) == NBLK - 1u) g_rel = target;
        else while (g_rel < target) { }
        __threadfence();
    }
    __syncthreads();
}

// ---- smem stage layout (fragment-major) ----
// A: 8 m8-groups x 2 ktiles, half-frag = 32 lanes * float2 (256B) -> 4KB
// B: 16 n8-groups, frag = 32 lanes * float4 (512B)               -> 8KB
#define ST_A_HI 0
#define ST_A_LO 4096
#define ST_B_HI 8192
#define ST_B_LO 16384
#define STAGE_BYTES 24576
#define SMEM_TOTAL (2 * STAGE_BYTES)

__device__ __forceinline__ uint32_t tf32_of(float x) {
    uint32_t u;
    asm("cvt.rna.tf32.f32 %0, %1;" : "=r"(u) : "f"(x));
    return u;
}
__device__ __forceinline__ float sigm(float x) { return 1.0f / (1.0f + expf(-x)); }

__device__ __forceinline__ void mma8(float d[4], const uint32_t a[4],
                                     uint32_t b0, uint32_t b1) {
    asm("mma.sync.aligned.m16n8k8.row.col.f32.tf32.tf32.f32 "
        "{%0,%1,%2,%3}, {%4,%5,%6,%7}, {%8,%9}, {%0,%1,%2,%3};"
        : "+f"(d[0]), "+f"(d[1]), "+f"(d[2]), "+f"(d[3])
        : "r"(a[0]), "r"(a[1]), "r"(a[2]), "r"(a[3]), "r"(b0), "r"(b1));
}

// split x -> (hi, lo) both tf32-rounded
__device__ __forceinline__ void split32(float x, uint32_t& hi, uint32_t& lo) {
    hi = tf32_of(x);
    lo = tf32_of(x - __uint_as_float(hi));
}

// C[M,N] = [A0 | A1*mask] @ [B0 | B1]^T + bias0 + bias1 (opt ELU), 3xTF32 mma.
__device__ void gemm_mma(char* smem, int M, int N,
                         const float* __restrict__ A0, int lda0, int K0,
                         const float* __restrict__ A1, int lda1, int K1,
                         const float* __restrict__ B0, int ldb0,
                         const float* __restrict__ B1, int ldb1,
                         const float* __restrict__ bias0,
                         const float* __restrict__ bias1,
                         const int* __restrict__ done_t,
                         float* __restrict__ C, int ldc, int act)
{
    const int tid = threadIdx.x;
    const int wid = tid >> 5, lane = tid & 31;
    const int warp_m = wid & 1;          // 2 m-groups of 32 rows
    const int warp_n = wid >> 1;         // 4 n-groups of 32 cols
    const int g = lane >> 2, tig = lane & 3;

    const int rowA = tid >> 2, jA = tid & 3;     // A writer: 64 rows x 4 j
    const int nB0  = tid >> 2, jB = tid & 3;     // B writer: rows nB0, nB0+64

    const int ntm = M / BM;
    const int ntn = (N + BN - 1) / BN;
    const int s0  = K0 / BK;
    const int nslab = s0 + K1 / BK;
    const bool hasmask = (done_t != nullptr);

    for (int u = blockIdx.x; u < ntm * ntn; u += NBLK) {
        const int m0 = (u % ntm) * BM;
        const int n0 = (u / ntm) * BN;
        const float mreg = hasmask ? (1.0f - (float)done_t[m0 + rowA]) : 1.0f;

        float d[2][4][4];
        #pragma unroll
        for (int a = 0; a < 2; a++)
            #pragma unroll
            for (int b = 0; b < 4; b++)
                #pragma unroll
                for (int c = 0; c < 4; c++) d[a][b][c] = 0.0f;

        float pa[4], pb[2][4];

        // ---- slab register load (k = jA + {0,4,8,12}) ----
        auto load_slab = [&](int s) {
            const float* As; int lda; bool mk;
            const float* Bs; int ldb;
            int kb;
            if (s < s0) { As = A0; lda = lda0; Bs = B0; ldb = ldb0; kb = s * BK; mk = false; }
            else        { As = A1; lda = lda1; Bs = B1; ldb = ldb1; kb = (s - s0) * BK; mk = hasmask; }
            const float* ap = As + (size_t)(m0 + rowA) * lda + kb + jA;
            pa[0] = ap[0]; pa[1] = ap[4]; pa[2] = ap[8]; pa[3] = ap[12];
            if (mk) { pa[0] *= mreg; pa[1] *= mreg; pa[2] *= mreg; pa[3] *= mreg; }
            #pragma unroll
            for (int it = 0; it < 2; it++) {
                int n = nB0 + it * 64;
                if (n0 + n < N) {
                    const float* bp = Bs + (size_t)(n0 + n) * ldb + kb + jB;
                    pb[it][0] = bp[0]; pb[it][1] = bp[4]; pb[it][2] = bp[8]; pb[it][3] = bp[12];
                } else {
                    pb[it][0] = pb[it][1] = pb[it][2] = pb[it][3] = 0.0f;
                }
            }
        };

        auto store_slab = [&](int st) {
            char* base = smem + st * STAGE_BYTES;
            uint32_t h0, l0, h1, l1, h2, l2, h3, l3;
            split32(pa[0], h0, l0); split32(pa[1], h1, l1);
            split32(pa[2], h2, l2); split32(pa[3], h3, l3);
            const int mg = rowA >> 3;
            const int off = ((rowA & 7) * 4 + jA) * 8;
            // ktile 0: (k=jA, jA+4) ; ktile 1: (jA+8, jA+12)
            *(uint2*)(base + ST_A_HI + (mg * 2 + 0) * 256 + off) = make_uint2(h0, h1);
            *(uint2*)(base + ST_A_HI + (mg * 2 + 1) * 256 + off) = make_uint2(h2, h3);
            *(uint2*)(base + ST_A_LO + (mg * 2 + 0) * 256 + off) = make_uint2(l0, l1);
            *(uint2*)(base + ST_A_LO + (mg * 2 + 1) * 256 + off) = make_uint2(l2, l3);
            #pragma unroll
            for (int it = 0; it < 2; it++) {
                int n = nB0 + it * 64;
                uint32_t bh[4], bl[4];
                split32(pb[it][0], bh[0], bl[0]); split32(pb[it][1], bh[1], bl[1]);
                split32(pb[it][2], bh[2], bl[2]); split32(pb[it][3], bh[3], bl[3]);
                const int boff = (n >> 3) * 512 + ((n & 7) * 4 + jB) * 16;
                *(uint4*)(base + ST_B_HI + boff) = make_uint4(bh[0], bh[1], bh[2], bh[3]);
                *(uint4*)(base + ST_B_LO + boff) = make_uint4(bl[0], bl[1], bl[2], bl[3]);
            }
        };

        load_slab(0);
        store_slab(0);
        __syncthreads();

        for (int s = 0; s < nslab; s++) {
            if (s + 1 < nslab) load_slab(s + 1);

            // ---- compute from stage s&1 ----
            {
                char* base = smem + (s & 1) * STAGE_BYTES;
                uint4 bhi[4], blo[4];
                #pragma unroll
                for (int nt = 0; nt < 4; nt++) {
                    const int ng = warp_n * 4 + nt;
                    bhi[nt] = *(const uint4*)(base + ST_B_HI + ng * 512 + lane * 16);
                    blo[nt] = *(const uint4*)(base + ST_B_LO + ng * 512 + lane * 16);
                }
                #pragma unroll
                for (int kt = 0; kt < 2; kt++) {
                    uint32_t ahi[2][4], alo[2][4];
                    #pragma unroll
                    for (int mt = 0; mt < 2; mt++) {
                        const int mg0 = (warp_m * 2 + mt) * 2;       // two m8 groups
                        uint2 v;
                        v = *(const uint2*)(base + ST_A_HI + ((mg0 + 0) * 2 + kt) * 256 + lane * 8);
                        ahi[mt][0] = v.x; ahi[mt][2] = v.y;
                        v = *(const uint2*)(base + ST_A_HI + ((mg0 + 1) * 2 + kt) * 256 + lane * 8);
                        ahi[mt][1] = v.x; ahi[mt][3] = v.y;
                        v = *(const uint2*)(base + ST_A_LO + ((mg0 + 0) * 2 + kt) * 256 + lane * 8);
                        alo[mt][0] = v.x; alo[mt][2] = v.y;
                        v = *(const uint2*)(base + ST_A_LO + ((mg0 + 1) * 2 + kt) * 256 + lane * 8);
                        alo[mt][1] = v.x; alo[mt][3] = v.y;
                    }
                    #pragma unroll
                    for (int mt = 0; mt < 2; mt++)
                        #pragma unroll
                        for (int nt = 0; nt < 4; nt++) {
                            uint32_t b0h = kt ? bhi[nt].z : bhi[nt].x;
                            uint32_t b1h = kt ? bhi[nt].w : bhi[nt].y;
                            uint32_t b0l = kt ? blo[nt].z : blo[nt].x;
                            uint32_t b1l = kt ? blo[nt].w : blo[nt].y;
                            mma8(d[mt][nt], ahi[mt], b0h, b1h);
                            mma8(d[mt][nt], ahi[mt], b0l, b1l);
                            mma8(d[mt][nt], alo[mt], b0h, b1h);
                        }
                }
            }

            if (s + 1 < nslab) store_slab((s + 1) & 1);
            __syncthreads();
        }

        // ---- epilogue ----
        #pragma unroll
        for (int mt = 0; mt < 2; mt++) {
            const int r0 = m0 + warp_m * 32 + mt * 16 + g;
            #pragma unroll
            for (int nt = 0; nt < 4; nt++) {
                const int c = n0 + warp_n * 32 + nt * 8 + 2 * tig;
                if (c < N) {
                    float b0v = bias0 ? bias0[c]     : 0.0f;
                    float b1v = bias0 ? bias0[c + 1] : 0.0f;
                    if (bias1) { b0v += bias1[c]; b1v += bias1[c + 1]; }
                    float v0 = d[mt][nt][0] + b0v, v1 = d[mt][nt][1] + b1v;
                    float v2 = d[mt][nt][2] + b0v, v3 = d[mt][nt][3] + b1v;
                    if (act) {
                        v0 = v0 > 0.f ? v0 : expm1f(v0);
                        v1 = v1 > 0.f ? v1 : expm1f(v1);
                        v2 = v2 > 0.f ? v2 : expm1f(v2);
                        v3 = v3 > 0.f ? v3 : expm1f(v3);
                    }
                    *(float2*)(C + (size_t)r0 * ldc + c)       = make_float2(v0, v1);
                    *(float2*)(C + (size_t)(r0 + 8) * ldc + c) = make_float2(v2, v3);
                }
            }
        }
        __syncthreads();
    }
}

// Pointwise LSTM cell from g_gates. Gate order i,f,g,o.
__device__ void cell_phase(float* h_state, float* c_state,
                           const int* done_t, float* hs_out)
{
    const int stride = NBLK * NTHR;
    for (int idx = blockIdx.x * NTHR + threadIdx.x; idx < BATCH * HID; idx += stride) {
        const int b = idx >> 10;
        const int j = idx & (HID - 1);
        const float m = 1.0f - (float)done_t[b];
        const float* gp = g_gates + (size_t)b * GATES;
        const float ig = sigm(gp[j]);
        const float fg = sigm(gp[HID + j]);
        const float gg = tanhf(gp[2 * HID + j]);
        const float og = sigm(gp[3 * HID + j]);
        const float c = fg * (c_state[idx] * m) + ig * gg;
        const float h = og * tanhf(c);
        c_state[idx] = c;
        h_state[idx] = h;
        if (hs_out) hs_out[idx] = h;
    }
}

__device__ void layernorm_phase(const float* __restrict__ gamma,
                                const float* __restrict__ beta)
{
    const int gwid = (blockIdx.x * NTHR + threadIdx.x) >> 5;
    const int lane = threadIdx.x & 31;
    const int nwarps = NBLK * NTHR / 32;
    for (int r = gwid; r < SEQ * BATCH; r += nwarps) {
        float* row = g_hs + (size_t)r * HID;
        float s = 0.f, ss = 0.f;
        for (int j = lane; j < HID; j += 32) { float v = row[j]; s += v; ss += v * v; }
        #pragma unroll
        for (int o = 16; o; o >>= 1) {
            s  += __shfl_xor_sync(0xffffffffu, s, o);
            ss += __shfl_xor_sync(0xffffffffu, ss, o);
        }
        const float mu   = s * (1.0f / HID);
        const float var  = ss * (1.0f / HID) - mu * mu;
        const float rstd = rsqrtf(var + 1e-5f);
        for (int j = lane; j < HID; j += 32)
            row[j] = (row[j] - mu) * rstd * gamma[j] + beta[j];
    }
}

__global__ __launch_bounds__(NTHR)
void critic_kernel(
    const float* __restrict__ x, const int* __restrict__ done,
    const float* __restrict__ h0, const float* __restrict__ c0,
    const float* __restrict__ Wih0, const float* __restrict__ Whh0,
    const float* __restrict__ bih0, const float* __restrict__ bhh0,
    const float* __restrict__ Wih1, const float* __restrict__ Whh1,
    const float* __restrict__ bih1, const float* __restrict__ bhh1,
    const float* __restrict__ lng,  const float* __restrict__ lnb,
    const float* __restrict__ W1,   const float* __restrict__ b1,
    const float* __restrict__ W2,   const float* __restrict__ b2,
    const float* __restrict__ W3,   const float* __restrict__ b3,
    const float* __restrict__ Wv,   const float* __restrict__ bv,
    float* __restrict__ out, int out_size)
{
    extern __shared__ char smem[];
    const int stride = NBLK * NTHR;
    const int gtid = blockIdx.x * NTHR + threadIdx.x;

    for (int i = gtid; i < 2 * BATCH * HID; i += stride) { g_h[i] = h0[i]; g_c[i] = c0[i]; }
    grid_sync();

    for (int t = 0; t < SEQ; ++t) {
        const int* dt = done + t * BATCH;

        gemm_mma(smem, BATCH, GATES,
                 x + (size_t)t * BATCH * OBS, OBS, OBS,
                 g_h, HID, HID,
                 Wih0, OBS, Whh0, HID,
                 bih0, bhh0, dt, g_gates, GATES, 0);
        grid_sync();
        cell_phase(g_h, g_c, dt, nullptr);
        grid_sync();

        gemm_mma(smem, BATCH, GATES,
                 g_h, HID, HID,
                 g_h + BATCH * HID, HID, HID,
                 Wih1, HID, Whh1, HID,
                 bih1, bhh1, dt, g_gates, GATES, 0);
        grid_sync();
        cell_phase(g_h + BATCH * HID, g_c + BATCH * HID, dt,
                   g_hs + (size_t)t * BATCH * HID);
        grid_sync();
    }

    layernorm_phase(lng, lnb);
    grid_sync();

    gemm_mma(smem, SEQ * BATCH, 512, g_hs, HID, HID, nullptr, 0, 0,
             W1, HID, nullptr, 0, b1, nullptr, nullptr, g_a1, 512, 1);
    grid_sync();
    gemm_mma(smem, SEQ * BATCH, 128, g_a1, 512, 512, nullptr, 0, 0,
             W2, 512, nullptr, 0, b2, nullptr, nullptr, g_a2, 128, 1);
    grid_sync();
    gemm_mma(smem, SEQ * BATCH, 64, g_a2, 128, 128, nullptr, 0, 0,
             W3, 128, nullptr, 0, b3, nullptr, nullptr, g_a3, 64, 1);
    grid_sync();

    for (int r = gtid; r < SEQ * BATCH; r += stride) {
        const float* a = g_a3 + (size_t)r * 64;
        float s = bv[0];
        #pragma unroll
        for (int k = 0; k < 64; k++) s += a[k] * Wv[k];
        out[r] = s;
    }
    if (out_size >= SEQ * BATCH + 4 * BATCH * HID) {
        float* oh = out + SEQ * BATCH;
        float* oc = oh + 2 * BATCH * HID;
        for (int i = gtid; i < 2 * BATCH * HID; i += stride) {
            oh[i] = g_h[i];
            oc[i] = g_c[i];
        }
    }
}

extern "C" void kernel_launch(void* const* d_in, const int* in_sizes, int n_in,
                              void* d_out, int out_size)
{
    cudaFuncSetAttribute(critic_kernel,
                         cudaFuncAttributeMaxDynamicSharedMemorySize, SMEM_TOTAL);
    critic_kernel<<<NBLK, NTHR, SMEM_TOTAL>>>(
        (const float*)d_in[0],  (const int*)d_in[1],
        (const float*)d_in[2],  (const float*)d_in[3],
        (const float*)d_in[4],  (const float*)d_in[5],
        (const float*)d_in[6],  (const float*)d_in[7],
        (const float*)d_in[8],  (const float*)d_in[9],
        (const float*)d_in[10], (const float*)d_in[11],
        (const float*)d_in[12], (const float*)d_in[13],
        (const float*)d_in[14], (const float*)d_in[15],
        (const float*)d_in[16], (const float*)d_in[17],
        (const float*)d_in[18], (const float*)d_in[19],
        (const float*)d_in[20], (const float*)d_in[21],
        (float*)d_out, out_size);
}

// round 12
// speedup vs baseline: 2.0708x; 1.9382x over previous
#include <cuda_runtime.h>
#include <cstdint>
#include <cstddef>

#define SEQ   128
#define BATCH 256
#define OBS   64
#define HID   1024
#define GATES 4096
#define NBLK  128
#define NTHR  512

// ---- device scratch ----
__device__ float g_h[2 * BATCH * HID];
__device__ float g_c[2 * BATCH * HID];
__device__ float g_gates[BATCH * GATES];
__device__ float g_hs[(size_t)SEQ * BATCH * HID];
__device__ float g_a1[(size_t)SEQ * BATCH * 512];
__device__ float g_a2[(size_t)SEQ * BATCH * 128];
__device__ float g_a3[(size_t)SEQ * BATCH * 64];

// ---- prepacked weight fragments (bf16 hi/lo, mma-fragment-major) ----
// one uint4 per lane per (n8-group, k16-slab): {hi.r0, hi.r1, lo.r0, lo.r1}
__device__ uint4 pk_ih0[(size_t)2048  * 32];   // Wih0: 512 ng * 4 slabs
__device__ uint4 pk_hh0[(size_t)32768 * 32];   // Whh0: 512 ng * 64
__device__ uint4 pk_ih1[(size_t)32768 * 32];   // Wih1
__device__ uint4 pk_hh1[(size_t)32768 * 32];   // Whh1
__device__ uint4 pk_W1 [(size_t)4096  * 32];   // W1: 64 ng * 64
__device__ uint4 pk_W2 [(size_t)512   * 32];   // W2: 16 ng * 32
__device__ uint4 pk_W3 [(size_t)64    * 32];   // W3: 8 ng * 8

// ---- grid barrier: monotonic, graph-replay-safe ----
__device__ unsigned g_arr = 0;
__device__ volatile unsigned g_rel = 0;

__device__ __forceinline__ void grid_sync() {
    __syncthreads();
    if (threadIdx.x == 0) {
        __threadfence();
        unsigned v = atomicAdd(&g_arr, 1u);
        unsigned target = v / NBLK + 1u;
        if ((v % NBLK) == NBLK - 1u) g_rel = target;
        else while (g_rel < target) { }
        __threadfence();
    }
    __syncthreads();
}

__device__ __forceinline__ float sigm(float x) { return 1.0f / (1.0f + expf(-x)); }

// pack (x0,x1) -> bf16x2 hi (x0 in low half), and bf16x2 lo of the residuals
__device__ __forceinline__ uint32_t bfsplit(float x0, float x1, uint32_t& lo) {
    uint32_t h;
    asm("cvt.rn.bf16x2.f32 %0, %1, %2;" : "=r"(h) : "f"(x1), "f"(x0));
    float h0 = __uint_as_float(h << 16);
    float h1 = __uint_as_float(h & 0xFFFF0000u);
    float l0 = x0 - h0, l1 = x1 - h1;
    asm("cvt.rn.bf16x2.f32 %0, %1, %2;" : "=r"(lo) : "f"(l1), "f"(l0));
    return h;
}

__device__ __forceinline__ void mma16(float d[4], const uint32_t a[4],
                                      uint32_t b0, uint32_t b1) {
    asm("mma.sync.aligned.m16n8k16.row.col.f32.bf16.bf16.f32 "
        "{%0,%1,%2,%3}, {%4,%5,%6,%7}, {%8,%9}, {%0,%1,%2,%3};"
        : "+f"(d[0]), "+f"(d[1]), "+f"(d[2]), "+f"(d[3])
        : "r"(a[0]), "r"(a[1]), "r"(a[2]), "r"(a[3]), "r"(b0), "r"(b1));
}

// ---- weight prepack: run once per launch ----
#define NFRAG_TOTAL 105024
__global__ __launch_bounds__(NTHR) void prepack_kernel(
    const float* __restrict__ Wih0, const float* __restrict__ Whh0,
    const float* __restrict__ Wih1, const float* __restrict__ Whh1,
    const float* __restrict__ W1,  const float* __restrict__ W2,
    const float* __restrict__ W3)
{
    const int total = NFRAG_TOTAL * 32;
    for (int t = blockIdx.x * blockDim.x + threadIdx.x; t < total;
         t += gridDim.x * blockDim.x) {
        const int f = t >> 5, lane = t & 31;
        const float* W; uint4* pk; int ns, K, fl;
        if      (f < 2048)   { W = Wih0; pk = pk_ih0; ns = 4;  K = 64;   fl = f; }
        else if (f < 34816)  { W = Whh0; pk = pk_hh0; ns = 64; K = 1024; fl = f - 2048; }
        else if (f < 67584)  { W = Wih1; pk = pk_ih1; ns = 64; K = 1024; fl = f - 34816; }
        else if (f < 100352) { W = Whh1; pk = pk_hh1; ns = 64; K = 1024; fl = f - 67584; }
        else if (f < 104448) { W = W1;   pk = pk_W1;  ns = 64; K = 1024; fl = f - 100352; }
        else if (f < 104960) { W = W2;   pk = pk_W2;  ns = 32; K = 512;  fl = f - 104448; }
        else                 { W = W3;   pk = pk_W3;  ns = 8;  K = 128;  fl = f - 104960; }
        const int ng = fl / ns, s = fl - ng * ns;
        const int g = lane >> 2, tig = lane & 3;
        const float* wp = W + (size_t)(ng * 8 + g) * K + s * 16 + 2 * tig;
        uint32_t l01, l23;
        uint32_t h01 = bfsplit(wp[0], wp[1], l01);
        uint32_t h23 = bfsplit(wp[8], wp[9], l23);
        pk[(size_t)fl * 32 + lane] = make_uint4(h01, h23, l01, l23);
    }
}

// C[M,N] = [A0 | A1*mask] @ [B0 | B1]^T + bias0 + bias1 (opt ELU).
// 3-term bf16-split mma (hi*hi + hi*lo + lo*hi), fp32 accum.
// CTA tile 64x128, 16 warps (4m x 4n), warp tile 16x32, k16 slabs.
// B fragments stream directly from prepacked global (LDG.128/frag, no smem).
__device__ void gemm_mma(int M, int N,
                         const float* __restrict__ A0, int lda0, int K0,
                         const float* __restrict__ A1, int lda1, int K1,
                         const uint4* __restrict__ PK0,
                         const uint4* __restrict__ PK1,
                         const float* __restrict__ bias0,
                         const float* __restrict__ bias1,
                         const int* __restrict__ done_t,
                         float* __restrict__ C, int ldc, int act)
{
    __shared__ __align__(16) char smem[2 * 4096];  // A stages: 4 m16-frags x 1KB
    const int tid = threadIdx.x, lane = tid & 31, wid = tid >> 5;
    const int warp_m = wid & 3, warp_n = wid >> 2;
    const int g = lane >> 2, tig = lane & 3;
    const int ns0 = K0 / 16, ns1 = K1 / 16, ns = ns0 + ns1;
    const int ntm = M / 64, ntn = (N + 127) / 128;
    // A-writer role: 256 tasks = 4 frags x 32 lanes x 2 k-halves
    const bool wr = tid < 256;
    const int wf = tid >> 6, wl = (tid >> 1) & 31, wh = tid & 1;
    const int wg = wl >> 2, wtig = wl & 3;

    for (int u = blockIdx.x; u < ntm * ntn; u += NBLK) {
        const int m0 = (u % ntm) * 64, n0 = (u / ntm) * 128;
        const int r1 = m0 + wf * 16 + wg, r2 = r1 + 8;
        float msk1 = 1.f, msk2 = 1.f;
        if (done_t && wr) {
            msk1 = 1.f - (float)done_t[r1];
            msk2 = 1.f - (float)done_t[r2];
        }

        float acc[4][4];
        #pragma unroll
        for (int i = 0; i < 4; i++)
            #pragma unroll
            for (int j = 0; j < 4; j++) acc[i][j] = 0.f;

        const int ngb = (n0 >> 3) + warp_n * 4;
        uint4 bq[4], bq2[4];
        float2 p1, p2;

        auto ldB = [&](int s, uint4* q) {
            #pragma unroll
            for (int nt = 0; nt < 4; nt++) {
                const int ng = ngb + nt;
                if (ng * 8 < N) {
                    const uint4* p = (s < ns0)
                        ? PK0 + ((size_t)ng * ns0 + s) * 32 + lane
                        : PK1 + ((size_t)ng * ns1 + (s - ns0)) * 32 + lane;
                    q[nt] = *p;
                } else q[nt] = make_uint4(0u, 0u, 0u, 0u);
            }
        };
        auto ldA = [&](int s) {
            if (!wr) return;
            const float* src; int lda; int kb; bool mk;
            if (s < ns0) { src = A0; lda = lda0; kb = s * 16; mk = false; }
            else { src = A1; lda = lda1; kb = (s - ns0) * 16; mk = (done_t != nullptr); }
            const float* pA = src + (size_t)r1 * lda + kb + wh * 8 + 2 * wtig;
            p1 = *(const float2*)pA;
            p2 = *(const float2*)(pA + (size_t)8 * lda);
            if (mk) { p1.x *= msk1; p1.y *= msk1; p2.x *= msk2; p2.y *= msk2; }
        };
        auto stA = [&](int st) {
            if (!wr) return;
            char* b = smem + st * 4096 + wf * 1024;
            uint32_t lo1, lo2;
            uint32_t hi1 = bfsplit(p1.x, p1.y, lo1);
            uint32_t hi2 = bfsplit(p2.x, p2.y, lo2);
            *(uint2*)(b + wh * 256 + wl * 8)       = make_uint2(hi1, hi2);
            *(uint2*)(b + 512 + wh * 256 + wl * 8) = make_uint2(lo1, lo2);
        };

        ldB(0, bq);
        ldA(0); stA(0);
        __syncthreads();

        for (int s = 0; s < ns; s++) {
            if (s + 1 < ns) { ldB(s + 1, bq2); ldA(s + 1); }

            const char* ab = smem + (s & 1) * 4096 + warp_m * 1024;
            uint2 h01 = *(const uint2*)(ab + lane * 8);
            uint2 h23 = *(const uint2*)(ab + 256 + lane * 8);
            uint2 l01 = *(const uint2*)(ab + 512 + lane * 8);
            uint2 l23 = *(const uint2*)(ab + 768 + lane * 8);
            uint32_t ah[4] = { h01.x, h01.y, h23.x, h23.y };
            uint32_t al[4] = { l01.x, l01.y, l23.x, l23.y };
            #pragma unroll
            for (int nt = 0; nt < 4; nt++) mma16(acc[nt], ah, bq[nt].x, bq[nt].y);
            #pragma unroll
            for (int nt = 0; nt < 4; nt++) mma16(acc[nt], ah, bq[nt].z, bq[nt].w);
            #pragma unroll
            for (int nt = 0; nt < 4; nt++) mma16(acc[nt], al, bq[nt].x, bq[nt].y);

            if (s + 1 < ns) stA((s + 1) & 1);
            __syncthreads();
            #pragma unroll
            for (int nt = 0; nt < 4; nt++) bq[nt] = bq2[nt];
        }

        const int rr = m0 + warp_m * 16 + g;
        #pragma unroll
        for (int nt = 0; nt < 4; nt++) {
            const int c = n0 + warp_n * 32 + nt * 8 + 2 * tig;
            if (c < N) {
                float b0v = bias0 ? bias0[c]     : 0.f;
                float b1v = bias0 ? bias0[c + 1] : 0.f;
                if (bias1) { b0v += bias1[c]; b1v += bias1[c + 1]; }
                float v0 = acc[nt][0] + b0v, v1 = acc[nt][1] + b1v;
                float v2 = acc[nt][2] + b0v, v3 = acc[nt][3] + b1v;
                if (act) {
                    v0 = v0 > 0.f ? v0 : expm1f(v0);
                    v1 = v1 > 0.f ? v1 : expm1f(v1);
                    v2 = v2 > 0.f ? v2 : expm1f(v2);
                    v3 = v3 > 0.f ? v3 : expm1f(v3);
                }
                *(float2*)(C + (size_t)rr * ldc + c)       = make_float2(v0, v1);
                *(float2*)(C + (size_t)(rr + 8) * ldc + c) = make_float2(v2, v3);
            }
        }
        __syncthreads();
    }
}

// Pointwise LSTM cell from g_gates. Gate order i,f,g,o.
__device__ void cell_phase(float* h_state, float* c_state,
                           const int* done_t, float* hs_out)
{
    const int stride = NBLK * NTHR;
    for (int idx = blockIdx.x * NTHR + threadIdx.x; idx < BATCH * HID; idx += stride) {
        const int b = idx >> 10;
        const int j = idx & (HID - 1);
        const float m = 1.0f - (float)done_t[b];
        const float* gp = g_gates + (size_t)b * GATES;
        const float ig = sigm(gp[j]);
        const float fg = sigm(gp[HID + j]);
        const float gg = tanhf(gp[2 * HID + j]);
        const float og = sigm(gp[3 * HID + j]);
        const float c = fg * (c_state[idx] * m) + ig * gg;
        const float h = og * tanhf(c);
        c_state[idx] = c;
        h_state[idx] = h;
        if (hs_out) hs_out[idx] = h;
    }
}

__device__ void layernorm_phase(const float* __restrict__ gamma,
                                const float* __restrict__ beta)
{
    const int gwid = (blockIdx.x * NTHR + threadIdx.x) >> 5;
    const int lane = threadIdx.x & 31;
    const int nwarps = NBLK * NTHR / 32;
    for (int r = gwid; r < SEQ * BATCH; r += nwarps) {
        float* row = g_hs + (size_t)r * HID;
        float s = 0.f, ss = 0.f;
        for (int j = lane; j < HID; j += 32) { float v = row[j]; s += v; ss += v * v; }
        #pragma unroll
        for (int o = 16; o; o >>= 1) {
            s  += __shfl_xor_sync(0xffffffffu, s, o);
            ss += __shfl_xor_sync(0xffffffffu, ss, o);
        }
        const float mu   = s * (1.0f / HID);
        const float var  = ss * (1.0f / HID) - mu * mu;
        const float rstd = rsqrtf(var + 1e-5f);
        for (int j = lane; j < HID; j += 32)
            row[j] = (row[j] - mu) * rstd * gamma[j] + beta[j];
    }
}

__global__ __launch_bounds__(NTHR)
void critic_kernel(
    const float* __restrict__ x, const int* __restrict__ done,
    const float* __restrict__ h0, const float* __restrict__ c0,
    const float* __restrict__ bih0, const float* __restrict__ bhh0,
    const float* __restrict__ bih1, const float* __restrict__ bhh1,
    const float* __restrict__ lng,  const float* __restrict__ lnb,
    const float* __restrict__ b1,   const float* __restrict__ b2,
    const float* __restrict__ b3,
    const float* __restrict__ Wv,   const float* __restrict__ bv,
    float* __restrict__ out, int out_size)
{
    const int stride = NBLK * NTHR;
    const int gtid = blockIdx.x * NTHR + threadIdx.x;

    for (int i = gtid; i < 2 * BATCH * HID; i += stride) { g_h[i] = h0[i]; g_c[i] = c0[i]; }
    grid_sync();

    for (int t = 0; t < SEQ; ++t) {
        const int* dt = done + t * BATCH;

        gemm_mma(BATCH, GATES,
                 x + (size_t)t * BATCH * OBS, OBS, OBS,
                 g_h, HID, HID,
                 pk_ih0, pk_hh0,
                 bih0, bhh0, dt, g_gates, GATES, 0);
        grid_sync();
        cell_phase(g_h, g_c, dt, nullptr);
        grid_sync();

        gemm_mma(BATCH, GATES,
                 g_h, HID, HID,
                 g_h + BATCH * HID, HID, HID,
                 pk_ih1, pk_hh1,
                 bih1, bhh1, dt, g_gates, GATES, 0);
        grid_sync();
        cell_phase(g_h + BATCH * HID, g_c + BATCH * HID, dt,
                   g_hs + (size_t)t * BATCH * HID);
        grid_sync();
    }

    layernorm_phase(lng, lnb);
    grid_sync();

    gemm_mma(SEQ * BATCH, 512, g_hs, HID, HID, nullptr, 0, 0,
             pk_W1, nullptr, b1, nullptr, nullptr, g_a1, 512, 1);
    grid_sync();
    gemm_mma(SEQ * BATCH, 128, g_a1, 512, 512, nullptr, 0, 0,
             pk_W2, nullptr, b2, nullptr, nullptr, g_a2, 128, 1);
    grid_sync();
    gemm_mma(SEQ * BATCH, 64, g_a2, 128, 128, nullptr, 0, 0,
             pk_W3, nullptr, b3, nullptr, nullptr, g_a3, 64, 1);
    grid_sync();

    for (int r = gtid; r < SEQ * BATCH; r += stride) {
        const float* a = g_a3 + (size_t)r * 64;
        float s = bv[0];
        #pragma unroll
        for (int k = 0; k < 64; k++) s += a[k] * Wv[k];
        out[r] = s;
    }
    if (out_size >= SEQ * BATCH + 4 * BATCH * HID) {
        float* oh = out + SEQ * BATCH;
        float* oc = oh + 2 * BATCH * HID;
        for (int i = gtid; i < 2 * BATCH * HID; i += stride) {
            oh[i] = g_h[i];
            oc[i] = g_c[i];
        }
    }
}

extern "C" void kernel_launch(void* const* d_in, const int* in_sizes, int n_in,
                              void* d_out, int out_size)
{
    prepack_kernel<<<NBLK, NTHR>>>(
        (const float*)d_in[4],  (const float*)d_in[5],
        (const float*)d_in[8],  (const float*)d_in[9],
        (const float*)d_in[14], (const float*)d_in[16],
        (const float*)d_in[18]);
    critic_kernel<<<NBLK, NTHR>>>(
        (const float*)d_in[0],  (const int*)d_in[1],
        (const float*)d_in[2],  (const float*)d_in[3],
        (const float*)d_in[6],  (const float*)d_in[7],
        (const float*)d_in[10], (const float*)d_in[11],
        (const float*)d_in[12], (const float*)d_in[13],
        (const float*)d_in[15], (const float*)d_in[17],
        (const float*)d_in[19],
        (const float*)d_in[20], (const float*)d_in[21],
        (float*)d_out, out_size);
}

// round 14
// speedup vs baseline: 2.2896x; 1.1057x over previous
#include <cuda_runtime.h>
#include <cstdint>
#include <cstddef>

#define SEQ   128
#define BATCH 256
#define OBS   64
#define HID   1024
#define GATES 4096
#define NBLK  128
#define NTHR  512
#define BH    (BATCH * HID)

// ---- fp32 scratch ----
__device__ float g_h[2 * BH];
__device__ float g_c[2 * BH];
__device__ float g_gates[BATCH * GATES];
__device__ float g_hs[(size_t)SEQ * BH];
__device__ float g_a3[(size_t)SEQ * BATCH * 64];

// ---- packed B (weights): uint4 {hi.r0,hi.r1,lo.r0,lo.r1} per lane per (n8,k16) frag
__device__ uint4 pk_ih0[(size_t)2048  * 32];
__device__ uint4 pk_hh0[(size_t)32768 * 32];
__device__ uint4 pk_ih1[(size_t)32768 * 32];
__device__ uint4 pk_hh1[(size_t)32768 * 32];
__device__ uint4 pk_W1 [(size_t)4096  * 32];
__device__ uint4 pk_W2 [(size_t)512   * 32];
__device__ uint4 pk_W3 [(size_t)64    * 32];

// ---- packed A (activations): per (m16,k16) frag, 64 uint4 = 32 lanes x {hi,lo}
__device__ uint4 g_xpack[(size_t)8192 * 64];          // [t][mg16][s4]
__device__ uint4 g_h0m [(size_t)1024 * 64];           // h0 * mask  [mg16][s64]
__device__ uint4 g_h0u [(size_t)1024 * 64];           // h0 unmasked
__device__ uint4 g_h1m [(size_t)1024 * 64];           // h1 * mask
__device__ uint4 g_hsp [(size_t)131072 * 64];         // LN(h) [mg2048][s64]
__device__ uint4 g_a1p [(size_t)65536 * 64];          // a1 [mg2048][s32]
__device__ uint4 g_a2p [(size_t)16384 * 64];          // a2 [mg2048][s8]

// ---- grid barrier: monotonic, graph-replay-safe ----
__device__ unsigned g_arr = 0;
__device__ volatile unsigned g_rel = 0;

__device__ __forceinline__ void grid_sync() {
    __syncthreads();
    if (threadIdx.x == 0) {
        __threadfence();
        unsigned v = atomicAdd(&g_arr, 1u);
        unsigned target = v / NBLK + 1u;
        if ((v % NBLK) == NBLK - 1u) g_rel = target;
        else while (g_rel < target) { }
        __threadfence();
    }
    __syncthreads();
}

__device__ __forceinline__ float sigm(float x) { return 1.0f / (1.0f + expf(-x)); }

// pack (x0,x1) -> bf16x2 hi (x0 low), lo of residuals
__device__ __forceinline__ uint32_t bfsplit(float x0, float x1, uint32_t& lo) {
    uint32_t h;
    asm("cvt.rn.bf16x2.f32 %0, %1, %2;" : "=r"(h) : "f"(x1), "f"(x0));
    float h0 = __uint_as_float(h << 16);
    float h1 = __uint_as_float(h & 0xFFFF0000u);
    float l0 = x0 - h0, l1 = x1 - h1;
    asm("cvt.rn.bf16x2.f32 %0, %1, %2;" : "=r"(lo) : "f"(l1), "f"(l0));
    return h;
}

__device__ __forceinline__ void mma16(float d[4], const uint32_t a[4],
                                      uint32_t b0, uint32_t b1) {
    asm("mma.sync.aligned.m16n8k16.row.col.f32.bf16.bf16.f32 "
        "{%0,%1,%2,%3}, {%4,%5,%6,%7}, {%8,%9}, {%0,%1,%2,%3};"
        : "+f"(d[0]), "+f"(d[1]), "+f"(d[2]), "+f"(d[3])
        : "r"(a[0]), "r"(a[1]), "r"(a[2]), "r"(a[3]), "r"(b0), "r"(b1));
}

// ---- prepack: weights (B frags) + x (A frags), once per launch ----
#define NWFRAG 105024
#define NFRAG  (NWFRAG + 8192)
__global__ __launch_bounds__(NTHR) void prepack_kernel(
    const float* __restrict__ Wih0, const float* __restrict__ Whh0,
    const float* __restrict__ Wih1, const float* __restrict__ Whh1,
    const float* __restrict__ W1,  const float* __restrict__ W2,
    const float* __restrict__ W3,  const float* __restrict__ x)
{
    const int total = NFRAG * 32;
    for (int t = blockIdx.x * blockDim.x + threadIdx.x; t < total;
         t += gridDim.x * blockDim.x) {
        const int f = t >> 5, lane = t & 31;
        const int g = lane >> 2, tig = lane & 3;
        if (f < NWFRAG) {
            const float* W; uint4* pk; int ns, K, fl;
            if      (f < 2048)   { W = Wih0; pk = pk_ih0; ns = 4;  K = 64;   fl = f; }
            else if (f < 34816)  { W = Whh0; pk = pk_hh0; ns = 64; K = 1024; fl = f - 2048; }
            else if (f < 67584)  { W = Wih1; pk = pk_ih1; ns = 64; K = 1024; fl = f - 34816; }
            else if (f < 100352) { W = Whh1; pk = pk_hh1; ns = 64; K = 1024; fl = f - 67584; }
            else if (f < 104448) { W = W1;   pk = pk_W1;  ns = 64; K = 1024; fl = f - 100352; }
            else if (f < 104960) { W = W2;   pk = pk_W2;  ns = 32; K = 512;  fl = f - 104448; }
            else                 { W = W3;   pk = pk_W3;  ns = 8;  K = 128;  fl = f - 104960; }
            const int ng = fl / ns, s = fl - ng * ns;
            const float* wp = W + (size_t)(ng * 8 + g) * K + s * 16 + 2 * tig;
            uint32_t l01, l23;
            uint32_t h01 = bfsplit(wp[0], wp[1], l01);
            uint32_t h23 = bfsplit(wp[8], wp[9], l23);
            pk[(size_t)fl * 32 + lane] = make_uint4(h01, h23, l01, l23);
        } else {
            const int fx = f - NWFRAG;                 // [t][mg][s]
            const int ts = fx >> 6, mg = (fx >> 2) & 15, s = fx & 3;
            const int r0 = ts * 256 + mg * 16 + g, r1 = r0 + 8;
            const int c0 = s * 16 + 2 * tig;
            const float* p0 = x + (size_t)r0 * OBS + c0;
            const float* p1 = x + (size_t)r1 * OBS + c0;
            uint32_t l0, l1, l2, l3;
            uint32_t a0 = bfsplit(p0[0], p0[1], l0);
            uint32_t a1 = bfsplit(p1[0], p1[1], l1);
            uint32_t a2 = bfsplit(p0[8], p0[9], l2);
            uint32_t a3 = bfsplit(p1[8], p1[9], l3);
            uint4* d = g_xpack + (size_t)fx * 64 + lane * 2;
            d[0] = make_uint4(a0, a1, a2, a3);
            d[1] = make_uint4(l0, l1, l2, l3);
        }
    }
}

// GEMM: C = A @ B^T (+bias, opt ELU). A = packed frags [Af0(ns0) | Af1(ns1)],
// B = packed frags. CTA 64x128, 16 warps (4m x 4n), warp tile 16x32.
// No smem, no block syncs. Output: f32 (C) or packed frags (Cp).
__device__ void gemm_mma(int M, int N,
                         const uint4* __restrict__ Af0, int ns0,
                         const uint4* __restrict__ Af1, int ns1,
                         const uint4* __restrict__ PK0,
                         const uint4* __restrict__ PK1,
                         const float* __restrict__ bias0,
                         const float* __restrict__ bias1,
                         float* __restrict__ C, int ldc, int act,
                         uint4* __restrict__ Cp, int nsCp)
{
    const int tid = threadIdx.x, lane = tid & 31, wid = tid >> 5;
    const int warp_m = wid & 3, warp_n = wid >> 2;
    const int g = lane >> 2, tg = lane & 3;
    const int ns = ns0 + ns1;
    const int ntm = M / 64, ntn = (N + 127) / 128;

    for (int u = blockIdx.x; u < ntm * ntn; u += NBLK) {
        const int m0 = (u % ntm) * 64, n0 = (u / ntm) * 128;
        const int mg = (m0 >> 4) + warp_m;
        const int ngb = (n0 >> 3) + warp_n * 4;
        const uint4* aB0 = Af0 + (size_t)mg * ns0 * 64 + lane * 2;
        const uint4* aB1 = Af1 ? (Af1 + (size_t)mg * ns1 * 64 + lane * 2) : nullptr;

        float acc[4][4];
        #pragma unroll
        for (int i = 0; i < 4; i++)
            #pragma unroll
            for (int j = 0; j < 4; j++) acc[i][j] = 0.f;

        uint4 ah, al, bq[4];
        auto ld = [&](int s, uint4& ah_, uint4& al_, uint4* q) {
            const uint4* p = (s < ns0) ? (aB0 + (size_t)s * 64)
                                       : (aB1 + (size_t)(s - ns0) * 64);
            ah_ = p[0]; al_ = p[1];
            #pragma unroll
            for (int nt = 0; nt < 4; nt++) {
                const int ng = ngb + nt;
                if (ng * 8 < N)
                    q[nt] = (s < ns0) ? PK0[((size_t)ng * ns0 + s) * 32 + lane]
                                      : PK1[((size_t)ng * ns1 + (s - ns0)) * 32 + lane];
                else q[nt] = make_uint4(0u, 0u, 0u, 0u);
            }
        };

        ld(0, ah, al, bq);
        for (int s = 0; s < ns; s++) {
            uint4 ah2, al2, bq2[4];
            if (s + 1 < ns) ld(s + 1, ah2, al2, bq2);
            uint32_t A_[4] = { ah.x, ah.y, ah.z, ah.w };
            uint32_t L_[4] = { al.x, al.y, al.z, al.w };
            #pragma unroll
            for (int nt = 0; nt < 4; nt++) mma16(acc[nt], A_, bq[nt].x, bq[nt].y);
            #pragma unroll
            for (int nt = 0; nt < 4; nt++) mma16(acc[nt], A_, bq[nt].z, bq[nt].w);
            #pragma unroll
            for (int nt = 0; nt < 4; nt++) mma16(acc[nt], L_, bq[nt].x, bq[nt].y);
            ah = ah2; al = al2;
            #pragma unroll
            for (int nt = 0; nt < 4; nt++) bq[nt] = bq2[nt];
        }

        #pragma unroll
        for (int nt = 0; nt < 4; nt++) {
            const int ng = ngb + nt;
            if (ng * 8 >= N) continue;
            const int c = n0 + warp_n * 32 + nt * 8 + 2 * tg;
            float b0v = bias0 ? bias0[c]     : 0.f;
            float b1v = bias0 ? bias0[c + 1] : 0.f;
            if (bias1) { b0v += bias1[c]; b1v += bias1[c + 1]; }
            float v0 = acc[nt][0] + b0v, v1 = acc[nt][1] + b1v;
            float v2 = acc[nt][2] + b0v, v3 = acc[nt][3] + b1v;
            if (act) {
                v0 = v0 > 0.f ? v0 : expm1f(v0);
                v1 = v1 > 0.f ? v1 : expm1f(v1);
                v2 = v2 > 0.f ? v2 : expm1f(v2);
                v3 = v3 > 0.f ? v3 : expm1f(v3);
            }
            if (Cp) {                               // packed A-frag output
                const int s = ng >> 1, kh = ng & 1;
                uint32_t l01, l23;
                uint32_t h01 = bfsplit(v0, v1, l01);
                uint32_t h23 = bfsplit(v2, v3, l23);
                char* bp = (char*)(Cp + ((size_t)mg * nsCp + s) * 64 + lane * 2);
                *(uint2*)(bp + kh * 8)      = make_uint2(h01, h23);
                *(uint2*)(bp + 16 + kh * 8) = make_uint2(l01, l23);
            } else {
                const int rr = m0 + warp_m * 16 + g;
                *(float2*)(C + (size_t)rr * ldc + c)       = make_float2(v0, v1);
                *(float2*)(C + (size_t)(rr + 8) * ldc + c) = make_float2(v2, v3);
            }
        }
    }
}

// LSTM cell: gates -> c,h (fp32) + packed h frags (unmasked and/or next-step-masked).
// 65536 threads, task = (mg, s, kh, lane): 2 rows x 2 cols.
__device__ void cell_phase(int layer, const int* __restrict__ done_t,
                           const int* __restrict__ done_next,
                           float* __restrict__ hs_out,
                           uint4* __restrict__ pk_u, uint4* __restrict__ pk_m)
{
    const int gt = blockIdx.x * NTHR + threadIdx.x;
    const int lane = gt & 31, kh = (gt >> 5) & 1, s = (gt >> 6) & 63, mg = gt >> 12;
    const int g = lane >> 2, tg = lane & 3;
    const int b0 = mg * 16 + g, b1 = b0 + 8;
    const int j = s * 16 + kh * 8 + 2 * tg;

    const float* gp0 = g_gates + (size_t)b0 * GATES + j;
    const float* gp1 = g_gates + (size_t)b1 * GATES + j;
    float2 i0 = *(const float2*)gp0,          i1 = *(const float2*)gp1;
    float2 f0 = *(const float2*)(gp0 + 1024), f1 = *(const float2*)(gp1 + 1024);
    float2 q0 = *(const float2*)(gp0 + 2048), q1 = *(const float2*)(gp1 + 2048);
    float2 o0 = *(const float2*)(gp0 + 3072), o1 = *(const float2*)(gp1 + 3072);

    float* cst = g_c + (size_t)layer * BH;
    float* hst = g_h + (size_t)layer * BH;
    const float m0r = 1.f - (float)done_t[b0];
    const float m1r = 1.f - (float)done_t[b1];
    float2 c0v = *(float2*)(cst + (size_t)b0 * HID + j);
    float2 c1v = *(float2*)(cst + (size_t)b1 * HID + j);

    float c00 = sigm(f0.x) * (c0v.x * m0r) + sigm(i0.x) * tanhf(q0.x);
    float c01 = sigm(f0.y) * (c0v.y * m0r) + sigm(i0.y) * tanhf(q0.y);
    float c10 = sigm(f1.x) * (c1v.x * m1r) + sigm(i1.x) * tanhf(q1.x);
    float c11 = sigm(f1.y) * (c1v.y * m1r) + sigm(i1.y) * tanhf(q1.y);
    float h00 = sigm(o0.x) * tanhf(c00), h01 = sigm(o0.y) * tanhf(c01);
    float h10 = sigm(o1.x) * tanhf(c10), h11 = sigm(o1.y) * tanhf(c11);

    *(float2*)(cst + (size_t)b0 * HID + j) = make_float2(c00, c01);
    *(float2*)(cst + (size_t)b1 * HID + j) = make_float2(c10, c11);
    *(float2*)(hst + (size_t)b0 * HID + j) = make_float2(h00, h01);
    *(float2*)(hst + (size_t)b1 * HID + j) = make_float2(h10, h11);
    if (hs_out) {
        *(float2*)(hs_out + (size_t)b0 * HID + j) = make_float2(h00, h01);
        *(float2*)(hs_out + (size_t)b1 * HID + j) = make_float2(h10, h11);
    }

    uint32_t lo0, lo1;
    uint32_t hi0 = bfsplit(h00, h01, lo0);
    uint32_t hi1 = bfsplit(h10, h11, lo1);
    const size_t fo = ((size_t)mg * 64 + s) * 64 + lane * 2;
    if (pk_u) {
        char* bp = (char*)(pk_u + fo);
        *(uint2*)(bp + kh * 8)      = make_uint2(hi0, hi1);
        *(uint2*)(bp + 16 + kh * 8) = make_uint2(lo0, lo1);
    }
    if (pk_m && done_next) {
        const uint32_t k0 = done_next[b0] ? 0u : 0xFFFFFFFFu;
        const uint32_t k1 = done_next[b1] ? 0u : 0xFFFFFFFFu;
        char* bp = (char*)(pk_m + fo);
        *(uint2*)(bp + kh * 8)      = make_uint2(hi0 & k0, hi1 & k1);
        *(uint2*)(bp + 16 + kh * 8) = make_uint2(lo0 & k0, lo1 & k1);
    }
}

// initial pack: h_init * mask0 -> h0m / h1m, plus fp32 h/c copy
__device__ void init_phase(const float* __restrict__ h0in,
                           const float* __restrict__ c0in,
                           const int* __restrict__ done0)
{
    const int gt = blockIdx.x * NTHR + threadIdx.x;
    for (int i = gt; i < 2 * BH; i += NBLK * NTHR) { g_h[i] = h0in[i]; g_c[i] = c0in[i]; }

    const int mi = gt >> 15, fx = gt & 32767;
    const int lane = fx & 31, s = (fx >> 5) & 63, mg = fx >> 11;
    const int g = lane >> 2, tg = lane & 3;
    const int b0 = mg * 16 + g, b1 = b0 + 8;
    const int c0 = s * 16 + 2 * tg;
    const float m0r = 1.f - (float)done0[b0];
    const float m1r = 1.f - (float)done0[b1];
    const float* p0 = h0in + (size_t)mi * BH + (size_t)b0 * HID + c0;
    const float* p1 = h0in + (size_t)mi * BH + (size_t)b1 * HID + c0;
    uint32_t l0, l1, l2, l3;
    uint32_t a0 = bfsplit(p0[0] * m0r, p0[1] * m0r, l0);
    uint32_t a1 = bfsplit(p1[0] * m1r, p1[1] * m1r, l1);
    uint32_t a2 = bfsplit(p0[8] * m0r, p0[9] * m0r, l2);
    uint32_t a3 = bfsplit(p1[8] * m1r, p1[9] * m1r, l3);
    uint4* d = (mi ? g_h1m : g_h0m) + ((size_t)mg * 64 + s) * 64 + lane * 2;
    d[0] = make_uint4(a0, a1, a2, a3);
    d[1] = make_uint4(l0, l1, l2, l3);
}

// LayerNorm + pack: warp per 16-row group, writes g_hsp frags
__device__ void layernorm_pack(const float* __restrict__ gamma,
                               const float* __restrict__ beta)
{
    const int mg = (blockIdx.x * NTHR + threadIdx.x) >> 5;   // 0..2047
    const int lane = threadIdx.x & 31;
    const int g = lane >> 2, tg = lane & 3;
    const float* r0 = g_hs + ((size_t)mg * 16 + g) * HID;
    const float* r1 = r0 + (size_t)8 * HID;

    float s0 = 0.f, ss0 = 0.f, s1 = 0.f, ss1 = 0.f;
    for (int s = 0; s < 64; s++) {
        const int c = s * 16 + 2 * tg;
        float2 a = *(const float2*)(r0 + c), b = *(const float2*)(r0 + c + 8);
        float2 d = *(const float2*)(r1 + c), e = *(const float2*)(r1 + c + 8);
        s0 += a.x + a.y + b.x + b.y;  ss0 += a.x*a.x + a.y*a.y + b.x*b.x + b.y*b.y;
        s1 += d.x + d.y + e.x + e.y;  ss1 += d.x*d.x + d.y*d.y + e.x*e.x + e.y*e.y;
    }
    #pragma unroll
    for (int o = 1; o <= 2; o <<= 1) {
        s0  += __shfl_xor_sync(0xffffffffu, s0, o);
        ss0 += __shfl_xor_sync(0xffffffffu, ss0, o);
        s1  += __shfl_xor_sync(0xffffffffu, s1, o);
        ss1 += __shfl_xor_sync(0xffffffffu, ss1, o);
    }
    const float mu0 = s0 * (1.f/HID), mu1 = s1 * (1.f/HID);
    const float rs0 = rsqrtf(ss0 * (1.f/HID) - mu0*mu0 + 1e-5f);
    const float rs1 = rsqrtf(ss1 * (1.f/HID) - mu1*mu1 + 1e-5f);

    uint4* dst = g_hsp + (size_t)mg * 64 * 64 + lane * 2;
    for (int s = 0; s < 64; s++) {
        const int c = s * 16 + 2 * tg;
        float2 a = *(const float2*)(r0 + c), b = *(const float2*)(r0 + c + 8);
        float2 d = *(const float2*)(r1 + c), e = *(const float2*)(r1 + c + 8);
        float2 gc = *(const float2*)(gamma + c), gc8 = *(const float2*)(gamma + c + 8);
        float2 bc = *(const float2*)(beta + c),  bc8 = *(const float2*)(beta + c + 8);
        float n00 = (a.x - mu0) * rs0 * gc.x  + bc.x,  n01 = (a.y - mu0) * rs0 * gc.y  + bc.y;
        float n02 = (b.x - mu0) * rs0 * gc8.x + bc8.x, n03 = (b.y - mu0) * rs0 * gc8.y + bc8.y;
        float n10 = (d.x - mu1) * rs1 * gc.x  + bc.x,  n11 = (d.y - mu1) * rs1 * gc.y  + bc.y;
        float n12 = (e.x - mu1) * rs1 * gc8.x + bc8.x, n13 = (e.y - mu1) * rs1 * gc8.y + bc8.y;
        uint32_t l0, l1, l2, l3;
        uint32_t a0 = bfsplit(n00, n01, l0);
        uint32_t a1 = bfsplit(n10, n11, l1);
        uint32_t a2 = bfsplit(n02, n03, l2);
        uint32_t a3 = bfsplit(n12, n13, l3);
        dst[(size_t)s * 64]     = make_uint4(a0, a1, a2, a3);
        dst[(size_t)s * 64 + 1] = make_uint4(l0, l1, l2, l3);
    }
}

__global__ __launch_bounds__(NTHR)
void critic_kernel(
    const float* __restrict__ x, const int* __restrict__ done,
    const float* __restrict__ h0, const float* __restrict__ c0,
    const float* __restrict__ bih0, const float* __restrict__ bhh0,
    const float* __restrict__ bih1, const float* __restrict__ bhh1,
    const float* __restrict__ lng,  const float* __restrict__ lnb,
    const float* __restrict__ b1,   const float* __restrict__ b2,
    const float* __restrict__ b3,
    const float* __restrict__ Wv,   const float* __restrict__ bv,
    float* __restrict__ out, int out_size)
{
    const int stride = NBLK * NTHR;
    const int gtid = blockIdx.x * NTHR + threadIdx.x;

    init_phase(h0, c0, done);
    grid_sync();

    for (int t = 0; t < SEQ; ++t) {
        const int* dt = done + t * BATCH;
        const int* dn = (t + 1 < SEQ) ? done + (t + 1) * BATCH : nullptr;

        gemm_mma(BATCH, GATES,
                 g_xpack + (size_t)t * 4096, 4, g_h0m, 64,
                 pk_ih0, pk_hh0, bih0, bhh0,
                 g_gates, GATES, 0, nullptr, 0);
        grid_sync();
        cell_phase(0, dt, dn, nullptr, g_h0u, g_h0m);
        grid_sync();

        gemm_mma(BATCH, GATES,
                 g_h0u, 64, g_h1m, 64,
                 pk_ih1, pk_hh1, bih1, bhh1,
                 g_gates, GATES, 0, nullptr, 0);
        grid_sync();
        cell_phase(1, dt, dn, g_hs + (size_t)t * BH, nullptr, g_h1m);
        grid_sync();
    }

    layernorm_pack(lng, lnb);
    grid_sync();

    gemm_mma(SEQ * BATCH, 512, g_hsp, 64, nullptr, 0,
             pk_W1, nullptr, b1, nullptr, nullptr, 0, 1, g_a1p, 32);
    grid_sync();
    gemm_mma(SEQ * BATCH, 128, g_a1p, 32, nullptr, 0,
             pk_W2, nullptr, b2, nullptr, nullptr, 0, 1, g_a2p, 8);
    grid_sync();
    gemm_mma(SEQ * BATCH, 64, g_a2p, 8, nullptr, 0,
             pk_W3, nullptr, b3, nullptr, g_a3, 64, 1, nullptr, 0);
    grid_sync();

    for (int r = gtid; r < SEQ * BATCH; r += stride) {
        const float* a = g_a3 + (size_t)r * 64;
        float s = bv[0];
        #pragma unroll
        for (int k = 0; k < 64; k++) s += a[k] * Wv[k];
        out[r] = s;
    }
    if (out_size >= SEQ * BATCH + 4 * BH) {
        float* oh = out + SEQ * BATCH;
        float* oc = oh + 2 * BH;
        for (int i = gtid; i < 2 * BH; i += stride) {
            oh[i] = g_h[i];
            oc[i] = g_c[i];
        }
    }
}

extern "C" void kernel_launch(void* const* d_in, const int* in_sizes, int n_in,
                              void* d_out, int out_size)
{
    prepack_kernel<<<NBLK, NTHR>>>(
        (const float*)d_in[4],  (const float*)d_in[5],
        (const float*)d_in[8],  (const float*)d_in[9],
        (const float*)d_in[14], (const float*)d_in[16],
        (const float*)d_in[18], (const float*)d_in[0]);
    critic_kernel<<<NBLK, NTHR>>>(
        (const float*)d_in[0],  (const int*)d_in[1],
        (const float*)d_in[2],  (const float*)d_in[3],
        (const float*)d_in[6],  (const float*)d_in[7],
        (const float*)d_in[10], (const float*)d_in[11],
        (const float*)d_in[12], (const float*)d_in[13],
        (const float*)d_in[15], (const float*)d_in[17],
        (const float*)d_in[19],
        (const float*)d_in[20], (const float*)d_in[21],
        (float*)d_out, out_size);
}

// round 15
// speedup vs baseline: 2.7876x; 1.2175x over previous
#include <cuda_runtime.h>
#include <cstdint>
#include <cstddef>

#define SEQ   128
#define BATCH 256
#define OBS   64
#define HID   1024
#define GATES 4096
#define NBLK  128
#define NTHR  512
#define BH    (BATCH * HID)

// ---- fp32 scratch ----
__device__ float g_h[2 * BH];
__device__ float g_c[2 * BH];
__device__ float g_gates[BATCH * GATES];
__device__ float g_hs[(size_t)SEQ * BH];
__device__ float g_a3[(size_t)SEQ * BATCH * 64];

// ---- packed B (weights): uint4 {hi.r0,hi.r1,lo.r0,lo.r1} per lane per (n8,k16) frag
__device__ uint4 pk_ih0[(size_t)2048  * 32];
__device__ uint4 pk_hh0[(size_t)32768 * 32];
__device__ uint4 pk_ih1[(size_t)32768 * 32];
__device__ uint4 pk_hh1[(size_t)32768 * 32];
__device__ uint4 pk_W1 [(size_t)4096  * 32];
__device__ uint4 pk_W2 [(size_t)512   * 32];
__device__ uint4 pk_W3 [(size_t)64    * 32];

// ---- packed A (activations): per (m16,k16) frag, 64 uint4 = 32 lanes x {hi,lo}
__device__ uint4 g_xpack[(size_t)8192 * 64];
__device__ uint4 g_h0m [(size_t)1024 * 64];
__device__ uint4 g_h0u [(size_t)1024 * 64];
__device__ uint4 g_h1m [(size_t)1024 * 64];
__device__ uint4 g_hsp [(size_t)131072 * 64];
__device__ uint4 g_a1p [(size_t)65536 * 64];
__device__ uint4 g_a2p [(size_t)16384 * 64];

// ---- grid barrier ----
__device__ unsigned g_arr = 0;
__device__ volatile unsigned g_rel = 0;

__device__ __forceinline__ void grid_sync() {
    __syncthreads();
    if (threadIdx.x == 0) {
        __threadfence();
        unsigned v = atomicAdd(&g_arr, 1u);
        unsigned target = v / NBLK + 1u;
        if ((v % NBLK) == NBLK - 1u) g_rel = target;
        else while (g_rel < target) { }
        __threadfence();
    }
    __syncthreads();
}

__device__ __forceinline__ float sigm(float x) { return 1.0f / (1.0f + expf(-x)); }

__device__ __forceinline__ uint32_t smem_u32_of(const void* p) {
    uint32_t a;
    asm("{ .reg .u64 t; cvta.to.shared.u64 t, %1; cvt.u32.u64 %0, t; }" : "=r"(a) : "l"(p));
    return a;
}
__device__ __forceinline__ uint4 lds128(uint32_t a) {
    uint4 v;
    asm volatile("ld.shared.v4.u32 {%0,%1,%2,%3}, [%4];"
                 : "=r"(v.x), "=r"(v.y), "=r"(v.z), "=r"(v.w) : "r"(a));
    return v;
}
__device__ __forceinline__ void cpasync16(uint32_t dst, const void* src, uint32_t sz) {
    asm volatile("cp.async.cg.shared.global [%0], [%1], 16, %2;"
                 :: "r"(dst), "l"(src), "r"(sz) : "memory");
}
#define CP_COMMIT() asm volatile("cp.async.commit_group;" ::: "memory")
#define CP_WAIT2()  asm volatile("cp.async.wait_group 2;" ::: "memory")

// pack (x0,x1) -> bf16x2 hi (x0 low), lo of residuals
__device__ __forceinline__ uint32_t bfsplit(float x0, float x1, uint32_t& lo) {
    uint32_t h;
    asm("cvt.rn.bf16x2.f32 %0, %1, %2;" : "=r"(h) : "f"(x1), "f"(x0));
    float h0 = __uint_as_float(h << 16);
    float h1 = __uint_as_float(h & 0xFFFF0000u);
    float l0 = x0 - h0, l1 = x1 - h1;
    asm("cvt.rn.bf16x2.f32 %0, %1, %2;" : "=r"(lo) : "f"(l1), "f"(l0));
    return h;
}
__device__ __forceinline__ void mma16(float d[4], const uint32_t a[4],
                                      uint32_t b0, uint32_t b1) {
    asm("mma.sync.aligned.m16n8k16.row.col.f32.bf16.bf16.f32 "
        "{%0,%1,%2,%3}, {%4,%5,%6,%7}, {%8,%9}, {%0,%1,%2,%3};"
        : "+f"(d[0]), "+f"(d[1]), "+f"(d[2]), "+f"(d[3])
        : "r"(a[0]), "r"(a[1]), "r"(a[2]), "r"(a[3]), "r"(b0), "r"(b1));
}

// ---- prepack ----
#define NWFRAG 105024
#define NFRAG  (NWFRAG + 8192)
__global__ __launch_bounds__(NTHR) void prepack_kernel(
    const float* __restrict__ Wih0, const float* __restrict__ Whh0,
    const float* __restrict__ Wih1, const float* __restrict__ Whh1,
    const float* __restrict__ W1,  const float* __restrict__ W2,
    const float* __restrict__ W3,  const float* __restrict__ x)
{
    const int total = NFRAG * 32;
    for (int t = blockIdx.x * blockDim.x + threadIdx.x; t < total;
         t += gridDim.x * blockDim.x) {
        const int f = t >> 5, lane = t & 31;
        const int g = lane >> 2, tig = lane & 3;
        if (f < NWFRAG) {
            const float* W; uint4* pk; int ns, K, fl;
            if      (f < 2048)   { W = Wih0; pk = pk_ih0; ns = 4;  K = 64;   fl = f; }
            else if (f < 34816)  { W = Whh0; pk = pk_hh0; ns = 64; K = 1024; fl = f - 2048; }
            else if (f < 67584)  { W = Wih1; pk = pk_ih1; ns = 64; K = 1024; fl = f - 34816; }
            else if (f < 100352) { W = Whh1; pk = pk_hh1; ns = 64; K = 1024; fl = f - 67584; }
            else if (f < 104448) { W = W1;   pk = pk_W1;  ns = 64; K = 1024; fl = f - 100352; }
            else if (f < 104960) { W = W2;   pk = pk_W2;  ns = 32; K = 512;  fl = f - 104448; }
            else                 { W = W3;   pk = pk_W3;  ns = 8;  K = 128;  fl = f - 104960; }
            const int ng = fl / ns, s = fl - ng * ns;
            const float* wp = W + (size_t)(ng * 8 + g) * K + s * 16 + 2 * tig;
            uint32_t l01, l23;
            uint32_t h01 = bfsplit(wp[0], wp[1], l01);
            uint32_t h23 = bfsplit(wp[8], wp[9], l23);
            pk[(size_t)fl * 32 + lane] = make_uint4(h01, h23, l01, l23);
        } else {
            const int fx = f - NWFRAG;
            const int ts = fx >> 6, mg = (fx >> 2) & 15, s = fx & 3;
            const int r0 = ts * 256 + mg * 16 + g, r1 = r0 + 8;
            const int c0 = s * 16 + 2 * tig;
            const float* p0 = x + (size_t)r0 * OBS + c0;
            const float* p1 = x + (size_t)r1 * OBS + c0;
            uint32_t l0, l1, l2, l3;
            uint32_t a0 = bfsplit(p0[0], p0[1], l0);
            uint32_t a1 = bfsplit(p1[0], p1[1], l1);
            uint32_t a2 = bfsplit(p0[8], p0[9], l2);
            uint32_t a3 = bfsplit(p1[8], p1[9], l3);
            uint4* d = g_xpack + (size_t)fx * 64 + lane * 2;
            d[0] = make_uint4(a0, a1, a2, a3);
            d[1] = make_uint4(l0, l1, l2, l3);
        }
    }
}

// GEMM with cp.async 4-stage smem pipeline (A + B[nt0,1]) and 2-deep LDG
// register pipeline (B[nt2,3]). CTA 64x128, 16 warps (4m x 4n), warp 16x32.
// NOTE: all ns values used are multiples of 4 (68,128,64,32,8... all %4==0
// except 68 -> 68%4==0 yes). Stage count 4.
__device__ void gemm_mma(int M, int N,
                         const uint4* __restrict__ Af0, int ns0,
                         const uint4* __restrict__ Af1, int ns1,
                         const uint4* __restrict__ PK0,
                         const uint4* __restrict__ PK1,
                         const float* __restrict__ bias0,
                         const float* __restrict__ bias1,
                         float* __restrict__ C, int ldc, int act,
                         uint4* __restrict__ Cp, int nsCp)
{
    __shared__ __align__(16) char smbuf[4 * 8192];   // stage: A 4KB | B 4KB
    const uint32_t smb = smem_u32_of(smbuf);
    const int tid = threadIdx.x, lane = tid & 31, wid = tid >> 5;
    const int warp_m = wid & 3, warp_n = wid >> 2;
    const int g = lane >> 2, tg = lane & 3;
    const int ns = ns0 + ns1;
    const int ntm = M / 64, ntn = (N + 127) / 128;

    // cp.async role (fixed per thread)
    const bool isA = tid < 256;
    uint32_t dstoff; int mgl = 0, eA = 0, ngl = 0, eB = 0;
    if (isA) {
        mgl = tid >> 6; eA = tid & 63;
        dstoff = (uint32_t)(mgl * 1024 + (eA & 1) * 512 + (eA >> 1) * 16);
    } else {
        const int j = tid - 256;
        const int fr = j >> 5; eB = j & 31;
        ngl = (fr >> 1) * 4 + (fr & 1);
        dstoff = (uint32_t)(4096 + fr * 512 + eB * 16);
    }

    for (int u = blockIdx.x; u < ntm * ntn; u += NBLK) {
        const int m0 = (u % ntm) * 64, n0 = (u / ntm) * 128;
        const int mg0 = m0 >> 4;
        const int ngb = (n0 >> 3) + warp_n * 4;

        // per-unit source bases (strength-reduced: +64/+32 uint4 per slab)
        const uint4* srcA0 = nullptr; const uint4* srcA1 = nullptr;
        const uint4* srcB0 = nullptr; const uint4* srcB1 = nullptr;
        uint32_t bsz = 16;
        if (isA) {
            const int mgA = mg0 + mgl;
            srcA0 = Af0 + (size_t)mgA * ns0 * 64 + eA;
            if (Af1) srcA1 = Af1 + (size_t)mgA * ns1 * 64 + eA;
        } else {
            const int ngT = (n0 >> 3) + ngl;
            const bool bv = ngT * 8 < N;
            bsz = bv ? 16u : 0u;
            srcB0 = PK0 + (bv ? (size_t)ngT * ns0 * 32 : 0) + eB;
            if (PK1) srcB1 = PK1 + (bv ? (size_t)ngT * ns1 * 32 : 0) + eB;
        }
        // LDG B pointers for nt2, nt3
        const int ng2 = ngb + 2, ng3 = ngb + 3;
        const bool v2 = ng2 * 8 < N, v3 = ng3 * 8 < N;
        const uint4* pB2_0 = PK0 + (v2 ? (size_t)ng2 * ns0 * 32 : 0) + lane;
        const uint4* pB3_0 = PK0 + (v3 ? (size_t)ng3 * ns0 * 32 : 0) + lane;
        const uint4* pB2_1 = PK1 ? PK1 + (v2 ? (size_t)ng2 * ns1 * 32 : 0) + lane : nullptr;
        const uint4* pB3_1 = PK1 ? PK1 + (v3 ? (size_t)ng3 * ns1 * 32 : 0) + lane : nullptr;

        float acc[4][4];
        #pragma unroll
        for (int i = 0; i < 4; i++)
            #pragma unroll
            for (int j2 = 0; j2 < 4; j2++) acc[i][j2] = 0.f;

        uint4 q2a = make_uint4(0,0,0,0), q3a = q2a, q2b = q2a, q3b = q2a;

        auto ldg2 = [&](int s, uint4& q2, uint4& q3) {
            if (s >= ns) return;
            if (s < ns0) {
                if (v2) q2 = pB2_0[(size_t)s * 32];
                if (v3) q3 = pB3_0[(size_t)s * 32];
            } else {
                if (v2) q2 = pB2_1[(size_t)(s - ns0) * 32];
                if (v3) q3 = pB3_1[(size_t)(s - ns0) * 32];
            }
        };
        auto issue = [&](int s) {
            if (s < ns) {
                const uint32_t d = smb + (uint32_t)(s & 3) * 8192u + dstoff;
                const uint4* p;
                uint32_t sz;
                if (isA) {
                    p = (s < ns0) ? srcA0 + (size_t)s * 64
                                  : srcA1 + (size_t)(s - ns0) * 64;
                    sz = 16u;
                } else {
                    p = (s < ns0) ? srcB0 + (size_t)s * 32
                                  : srcB1 + (size_t)(s - ns0) * 32;
                    sz = bsz;
                }
                cpasync16(d, p, sz);
            }
            CP_COMMIT();
        };

        __syncthreads();            // previous unit's smem fully consumed
        ldg2(0, q2a, q3a);
        ldg2(1, q2b, q3b);
        issue(0); issue(1); issue(2);

        #pragma unroll 2
        for (int s = 0; s < ns; s++) {
            CP_WAIT2();
            __syncthreads();

            const uint32_t sb = smb + (uint32_t)(s & 3) * 8192u;
            const uint32_t aaddr = sb + (uint32_t)(warp_m << 10) + (uint32_t)(lane << 4);
            uint4 ah = lds128(aaddr);
            uint4 al = lds128(aaddr + 512u);
            uint4 b0 = lds128(sb + 4096u + (uint32_t)(warp_n << 10) + (uint32_t)(lane << 4));
            uint4 b1 = lds128(sb + 4096u + (uint32_t)(warp_n << 10) + 512u + (uint32_t)(lane << 4));
            const uint4 q2 = (s & 1) ? q2b : q2a;
            const uint4 q3 = (s & 1) ? q3b : q3a;

            uint32_t A_[4] = { ah.x, ah.y, ah.z, ah.w };
            uint32_t L_[4] = { al.x, al.y, al.z, al.w };
            mma16(acc[0], A_, b0.x, b0.y);
            mma16(acc[1], A_, b1.x, b1.y);
            mma16(acc[2], A_, q2.x, q2.y);
            mma16(acc[3], A_, q3.x, q3.y);
            mma16(acc[0], A_, b0.z, b0.w);
            mma16(acc[1], A_, b1.z, b1.w);
            mma16(acc[2], A_, q2.z, q2.w);
            mma16(acc[3], A_, q3.z, q3.w);
            mma16(acc[0], L_, b0.x, b0.y);
            mma16(acc[1], L_, b1.x, b1.y);
            mma16(acc[2], L_, q2.x, q2.y);
            mma16(acc[3], L_, q3.x, q3.y);

            if (s & 1) ldg2(s + 2, q2b, q3b);
            else       ldg2(s + 2, q2a, q3a);
            issue(s + 3);
        }

        // epilogue
        #pragma unroll
        for (int nt = 0; nt < 4; nt++) {
            const int ng = ngb + nt;
            if (ng * 8 >= N) continue;
            const int c = n0 + warp_n * 32 + nt * 8 + 2 * tg;
            float b0v = bias0 ? bias0[c]     : 0.f;
            float b1v = bias0 ? bias0[c + 1] : 0.f;
            if (bias1) { b0v += bias1[c]; b1v += bias1[c + 1]; }
            float v0 = acc[nt][0] + b0v, v1 = acc[nt][1] + b1v;
            float v2_ = acc[nt][2] + b0v, v3_ = acc[nt][3] + b1v;
            if (act) {
                v0  = v0  > 0.f ? v0  : expm1f(v0);
                v1  = v1  > 0.f ? v1  : expm1f(v1);
                v2_ = v2_ > 0.f ? v2_ : expm1f(v2_);
                v3_ = v3_ > 0.f ? v3_ : expm1f(v3_);
            }
            if (Cp) {
                const int sOut = ng >> 1, kh = ng & 1;
                const int mgA = mg0 + warp_m;
                uint32_t l01, l23;
                uint32_t h01 = bfsplit(v0, v1, l01);
                uint32_t h23 = bfsplit(v2_, v3_, l23);
                char* bp = (char*)(Cp + ((size_t)mgA * nsCp + sOut) * 64 + lane * 2);
                *(uint2*)(bp + kh * 8)      = make_uint2(h01, h23);
                *(uint2*)(bp + 16 + kh * 8) = make_uint2(l01, l23);
            } else {
                const int rr = m0 + warp_m * 16 + g;
                *(float2*)(C + (size_t)rr * ldc + c)       = make_float2(v0, v1);
                *(float2*)(C + (size_t)(rr + 8) * ldc + c) = make_float2(v2_, v3_);
            }
        }
    }
}

// LSTM cell (unchanged from R14)
__device__ void cell_phase(int layer, const int* __restrict__ done_t,
                           const int* __restrict__ done_next,
                           float* __restrict__ hs_out,
                           uint4* __restrict__ pk_u, uint4* __restrict__ pk_m)
{
    const int gt = blockIdx.x * NTHR + threadIdx.x;
    const int lane = gt & 31, kh = (gt >> 5) & 1, s = (gt >> 6) & 63, mg = gt >> 12;
    const int g = lane >> 2, tg = lane & 3;
    const int b0 = mg * 16 + g, b1 = b0 + 8;
    const int j = s * 16 + kh * 8 + 2 * tg;

    const float* gp0 = g_gates + (size_t)b0 * GATES + j;
    const float* gp1 = g_gates + (size_t)b1 * GATES + j;
    float2 i0 = *(const float2*)gp0,          i1 = *(const float2*)gp1;
    float2 f0 = *(const float2*)(gp0 + 1024), f1 = *(const float2*)(gp1 + 1024);
    float2 q0 = *(const float2*)(gp0 + 2048), q1 = *(const float2*)(gp1 + 2048);
    float2 o0 = *(const float2*)(gp0 + 3072), o1 = *(const float2*)(gp1 + 3072);

    float* cst = g_c + (size_t)layer * BH;
    float* hst = g_h + (size_t)layer * BH;
    const float m0r = 1.f - (float)done_t[b0];
    const float m1r = 1.f - (float)done_t[b1];
    float2 c0v = *(float2*)(cst + (size_t)b0 * HID + j);
    float2 c1v = *(float2*)(cst + (size_t)b1 * HID + j);

    float c00 = sigm(f0.x) * (c0v.x * m0r) + sigm(i0.x) * tanhf(q0.x);
    float c01 = sigm(f0.y) * (c0v.y * m0r) + sigm(i0.y) * tanhf(q0.y);
    float c10 = sigm(f1.x) * (c1v.x * m1r) + sigm(i1.x) * tanhf(q1.x);
    float c11 = sigm(f1.y) * (c1v.y * m1r) + sigm(i1.y) * tanhf(q1.y);
    float h00 = sigm(o0.x) * tanhf(c00), h01 = sigm(o0.y) * tanhf(c01);
    float h10 = sigm(o1.x) * tanhf(c10), h11 = sigm(o1.y) * tanhf(c11);

    *(float2*)(cst + (size_t)b0 * HID + j) = make_float2(c00, c01);
    *(float2*)(cst + (size_t)b1 * HID + j) = make_float2(c10, c11);
    *(float2*)(hst + (size_t)b0 * HID + j) = make_float2(h00, h01);
    *(float2*)(hst + (size_t)b1 * HID + j) = make_float2(h10, h11);
    if (hs_out) {
        *(float2*)(hs_out + (size_t)b0 * HID + j) = make_float2(h00, h01);
        *(float2*)(hs_out + (size_t)b1 * HID + j) = make_float2(h10, h11);
    }

    uint32_t lo0, lo1;
    uint32_t hi0 = bfsplit(h00, h01, lo0);
    uint32_t hi1 = bfsplit(h10, h11, lo1);
    const size_t fo = ((size_t)mg * 64 + s) * 64 + lane * 2;
    if (pk_u) {
        char* bp = (char*)(pk_u + fo);
        *(uint2*)(bp + kh * 8)      = make_uint2(hi0, hi1);
        *(uint2*)(bp + 16 + kh * 8) = make_uint2(lo0, lo1);
    }
    if (pk_m && done_next) {
        const uint32_t k0 = done_next[b0] ? 0u : 0xFFFFFFFFu;
        const uint32_t k1 = done_next[b1] ? 0u : 0xFFFFFFFFu;
        char* bp = (char*)(pk_m + fo);
        *(uint2*)(bp + kh * 8)      = make_uint2(hi0 & k0, hi1 & k1);
        *(uint2*)(bp + 16 + kh * 8) = make_uint2(lo0 & k0, lo1 & k1);
    }
}

__device__ void init_phase(const float* __restrict__ h0in,
                           const float* __restrict__ c0in,
                           const int* __restrict__ done0)
{
    const int gt = blockIdx.x * NTHR + threadIdx.x;
    for (int i = gt; i < 2 * BH; i += NBLK * NTHR) { g_h[i] = h0in[i]; g_c[i] = c0in[i]; }

    const int mi = gt >> 15, fx = gt & 32767;
    const int lane = fx & 31, s = (fx >> 5) & 63, mg = fx >> 11;
    const int g = lane >> 2, tg = lane & 3;
    const int b0 = mg * 16 + g, b1 = b0 + 8;
    const int c0 = s * 16 + 2 * tg;
    const float m0r = 1.f - (float)done0[b0];
    const float m1r = 1.f - (float)done0[b1];
    const float* p0 = h0in + (size_t)mi * BH + (size_t)b0 * HID + c0;
    const float* p1 = h0in + (size_t)mi * BH + (size_t)b1 * HID + c0;
    uint32_t l0, l1, l2, l3;
    uint32_t a0 = bfsplit(p0[0] * m0r, p0[1] * m0r, l0);
    uint32_t a1 = bfsplit(p1[0] * m1r, p1[1] * m1r, l1);
    uint32_t a2 = bfsplit(p0[8] * m0r, p0[9] * m0r, l2);
    uint32_t a3 = bfsplit(p1[8] * m1r, p1[9] * m1r, l3);
    uint4* d = (mi ? g_h1m : g_h0m) + ((size_t)mg * 64 + s) * 64 + lane * 2;
    d[0] = make_uint4(a0, a1, a2, a3);
    d[1] = make_uint4(l0, l1, l2, l3);
}

__device__ void layernorm_pack(const float* __restrict__ gamma,
                               const float* __restrict__ beta)
{
    const int mg = (blockIdx.x * NTHR + threadIdx.x) >> 5;
    const int lane = threadIdx.x & 31;
    const int g = lane >> 2, tg = lane & 3;
    const float* r0 = g_hs + ((size_t)mg * 16 + g) * HID;
    const float* r1 = r0 + (size_t)8 * HID;

    float s0 = 0.f, ss0 = 0.f, s1 = 0.f, ss1 = 0.f;
    for (int s = 0; s < 64; s++) {
        const int c = s * 16 + 2 * tg;
        float2 a = *(const float2*)(r0 + c), b = *(const float2*)(r0 + c + 8);
        float2 d = *(const float2*)(r1 + c), e = *(const float2*)(r1 + c + 8);
        s0 += a.x + a.y + b.x + b.y;  ss0 += a.x*a.x + a.y*a.y + b.x*b.x + b.y*b.y;
        s1 += d.x + d.y + e.x + e.y;  ss1 += d.x*d.x + d.y*d.y + e.x*e.x + e.y*e.y;
    }
    #pragma unroll
    for (int o = 1; o <= 2; o <<= 1) {
        s0  += __shfl_xor_sync(0xffffffffu, s0, o);
        ss0 += __shfl_xor_sync(0xffffffffu, ss0, o);
        s1  += __shfl_xor_sync(0xffffffffu, s1, o);
        ss1 += __shfl_xor_sync(0xffffffffu, ss1, o);
    }
    const float mu0 = s0 * (1.f/HID), mu1 = s1 * (1.f/HID);
    const float rs0 = rsqrtf(ss0 * (1.f/HID) - mu0*mu0 + 1e-5f);
    const float rs1 = rsqrtf(ss1 * (1.f/HID) - mu1*mu1 + 1e-5f);

    uint4* dst = g_hsp + (size_t)mg * 64 * 64 + lane * 2;
    for (int s = 0; s < 64; s++) {
        const int c = s * 16 + 2 * tg;
        float2 a = *(const float2*)(r0 + c), b = *(const float2*)(r0 + c + 8);
        float2 d = *(const float2*)(r1 + c), e = *(const float2*)(r1 + c + 8);
        float2 gc = *(const float2*)(gamma + c), gc8 = *(const float2*)(gamma + c + 8);
        float2 bc = *(const float2*)(beta + c),  bc8 = *(const float2*)(beta + c + 8);
        float n00 = (a.x - mu0) * rs0 * gc.x  + bc.x,  n01 = (a.y - mu0) * rs0 * gc.y  + bc.y;
        float n02 = (b.x - mu0) * rs0 * gc8.x + bc8.x, n03 = (b.y - mu0) * rs0 * gc8.y + bc8.y;
        float n10 = (d.x - mu1) * rs1 * gc.x  + bc.x,  n11 = (d.y - mu1) * rs1 * gc.y  + bc.y;
        float n12 = (e.x - mu1) * rs1 * gc8.x + bc8.x, n13 = (e.y - mu1) * rs1 * gc8.y + bc8.y;
        uint32_t l0, l1, l2, l3;
        uint32_t a0 = bfsplit(n00, n01, l0);
        uint32_t a1 = bfsplit(n10, n11, l1);
        uint32_t a2 = bfsplit(n02, n03, l2);
        uint32_t a3 = bfsplit(n12, n13, l3);
        dst[(size_t)s * 64]     = make_uint4(a0, a1, a2, a3);
        dst[(size_t)s * 64 + 1] = make_uint4(l0, l1, l2, l3);
    }
}

__global__ __launch_bounds__(NTHR)
void critic_kernel(
    const float* __restrict__ x, const int* __restrict__ done,
    const float* __restrict__ h0, const float* __restrict__ c0,
    const float* __restrict__ bih0, const float* __restrict__ bhh0,
    const float* __restrict__ bih1, const float* __restrict__ bhh1,
    const float* __restrict__ lng,  const float* __restrict__ lnb,
    const float* __restrict__ b1,   const float* __restrict__ b2,
    const float* __restrict__ b3,
    const float* __restrict__ Wv,   const float* __restrict__ bv,
    float* __restrict__ out, int out_size)
{
    const int stride = NBLK * NTHR;
    const int gtid = blockIdx.x * NTHR + threadIdx.x;

    init_phase(h0, c0, done);
    grid_sync();

    for (int t = 0; t < SEQ; ++t) {
        const int* dt = done + t * BATCH;
        const int* dn = (t + 1 < SEQ) ? done + (t + 1) * BATCH : nullptr;

        gemm_mma(BATCH, GATES,
                 g_xpack + (size_t)t * 4096, 4, g_h0m, 64,
                 pk_ih0, pk_hh0, bih0, bhh0,
                 g_gates, GATES, 0, nullptr, 0);
        grid_sync();
        cell_phase(0, dt, dn, nullptr, g_h0u, g_h0m);
        grid_sync();

        gemm_mma(BATCH, GATES,
                 g_h0u, 64, g_h1m, 64,
                 pk_ih1, pk_hh1, bih1, bhh1,
                 g_gates, GATES, 0, nullptr, 0);
        grid_sync();
        cell_phase(1, dt, dn, g_hs + (size_t)t * BH, nullptr, g_h1m);
        grid_sync();
    }

    layernorm_pack(lng, lnb);
    grid_sync();

    gemm_mma(SEQ * BATCH, 512, g_hsp, 64, nullptr, 0,
             pk_W1, nullptr, b1, nullptr, nullptr, 0, 1, g_a1p, 32);
    grid_sync();
    gemm_mma(SEQ * BATCH, 128, g_a1p, 32, nullptr, 0,
             pk_W2, nullptr, b2, nullptr, nullptr, 0, 1, g_a2p, 8);
    grid_sync();
    gemm_mma(SEQ * BATCH, 64, g_a2p, 8, nullptr, 0,
             pk_W3, nullptr, b3, nullptr, g_a3, 64, 1, nullptr, 0);
    grid_sync();

    for (int r = gtid; r < SEQ * BATCH; r += stride) {
        const float* a = g_a3 + (size_t)r * 64;
        float s = bv[0];
        #pragma unroll
        for (int k = 0; k < 64; k++) s += a[k] * Wv[k];
        out[r] = s;
    }
    if (out_size >= SEQ * BATCH + 4 * BH) {
        float* oh = out + SEQ * BATCH;
        float* oc = oh + 2 * BH;
        for (int i = gtid; i < 2 * BH; i += stride) {
            oh[i] = g_h[i];
            oc[i] = g_c[i];
        }
    }
}

extern "C" void kernel_launch(void* const* d_in, const int* in_sizes, int n_in,
                              void* d_out, int out_size)
{
    prepack_kernel<<<NBLK, NTHR>>>(
        (const float*)d_in[4],  (const float*)d_in[5],
        (const float*)d_in[8],  (const float*)d_in[9],
        (const float*)d_in[14], (const float*)d_in[16],
        (const float*)d_in[18], (const float*)d_in[0]);
    critic_kernel<<<NBLK, NTHR>>>(
        (const float*)d_in[0],  (const int*)d_in[1],
        (const float*)d_in[2],  (const float*)d_in[3],
        (const float*)d_in[6],  (const float*)d_in[7],
        (const float*)d_in[10], (const float*)d_in[11],
        (const float*)d_in[12], (const float*)d_in[13],
        (const float*)d_in[15], (const float*)d_in[17],
        (const float*)d_in[19],
        (const float*)d_in[20], (const float*)d_in[21],
        (float*)d_out, out_size);
}